// round 12
// baseline (speedup 1.0000x reference)
#include <cuda_runtime.h>
#include <cuda_bf16.h>
#include <math.h>
#include <stdint.h>

#define C 512
#define HWN 1024
#define CHW (C*HWN)

__device__ __align__(16) float d_G[1024];        // G[i*32+x]
__device__ float d_mean[C];
__device__ float d_scale[C];
__device__ __align__(16) float d_out32[CHW];     // [c][hw]
__device__ __align__(16) float d_out32T[CHW];    // [hw][c]
__device__ __align__(16) float d_sigT[CHW];      // [hw][c]
__device__ __align__(16) float d_ps[4*1024*9];   // per-ctile partial scores
__device__ __align__(16) __nv_bfloat16 d_wh[CHW], d_wl[CHW];          // W split (512x1024)
__device__ __align__(16) __nv_bfloat16 d_cath[2*CHW], d_catl[2*CHW];  // cat split, flat
__device__ __align__(16) float d_y[4*CHW];       // 4 k-split partials

__device__ __forceinline__ float tanhapx(float x) {
    float y; asm("tanh.approx.f32 %0, %1;" : "=f"(y) : "f"(x)); return y;
}
__device__ __forceinline__ float sig1(float v) {
    return fmaf(tanhapx(0.5f * v), 0.5f, 0.5f);
}
__device__ __forceinline__ uint32_t pack_bf2(float a, float b) {
    __nv_bfloat162 t(__float2bfloat16_rn(a), __float2bfloat16_rn(b));
    return *reinterpret_cast<uint32_t*>(&t);
}
__device__ __forceinline__ void split4(const float4& v, uint2& hi, uint2& lo) {
    float h0 = __bfloat162float(__float2bfloat16_rn(v.x));
    float h1 = __bfloat162float(__float2bfloat16_rn(v.y));
    float h2 = __bfloat162float(__float2bfloat16_rn(v.z));
    float h3 = __bfloat162float(__float2bfloat16_rn(v.w));
    hi = make_uint2(pack_bf2(h0, h1), pack_bf2(h2, h3));
    lo = make_uint2(pack_bf2(v.x - h0, v.y - h1), pack_bf2(v.z - h2, v.w - h3));
}

// ---- blocks 0..511: channel means + W bf16 split; block 512: gaussian weights ----
__global__ void k_init(const float* __restrict__ x, const float* __restrict__ wd) {
    int t = threadIdx.x;
    if (blockIdx.x == 512) {
        int i = t;
        if (i < 32) {
            float ev[32]; float s = 0.f;
            #pragma unroll
            for (int xx = 0; xx < 32; xx++) {
                float dd = (float)(xx - i);
                float e = expf(-dd * dd * (1.0f/4.5f));
                ev[xx] = e; s += e;
            }
            float inv = 1.f / s;
            #pragma unroll
            for (int xx = 0; xx < 32; xx++) d_G[i*32 + xx] = ev[xx] * inv;
        }
        return;
    }
    int c = blockIdx.x;
    float4 wv = *reinterpret_cast<const float4*>(wd + (size_t)c*1024 + t*4);
    uint2 hi, lo; split4(wv, hi, lo);
    *reinterpret_cast<uint2*>(&d_wh[(size_t)c*1024 + t*4]) = hi;
    *reinterpret_cast<uint2*>(&d_wl[(size_t)c*1024 + t*4]) = lo;
    float4 v = reinterpret_cast<const float4*>(x + c*HWN)[t];
    float s = v.x + v.y + v.z + v.w;
    #pragma unroll
    for (int o = 16; o > 0; o >>= 1) s += __shfl_xor_sync(~0u, s, o);
    __shared__ float red[8];
    if ((t & 31) == 0) red[t >> 5] = s;
    __syncthreads();
    if (t == 0) {
        float tot = 0.f;
        #pragma unroll
        for (int w = 0; w < 8; w++) tot += red[w];
        d_mean[c] = tot * (1.f/1024.f);
    }
}

// ---- SE ----
__global__ void k_se(const float* __restrict__ w1, const float* __restrict__ w2) {
    __shared__ float s[512], s1[32];
    int t = threadIdx.x;
    s[t] = d_mean[t];
    __syncthreads();
    int o = t >> 4, l = t & 15;
    float a = 0.f;
    #pragma unroll
    for (int j = 0; j < 8; j++) {
        int c = (l + j*16) * 4;
        float4 w = *reinterpret_cast<const float4*>(w1 + o*512 + c);
        a += w.x*s[c] + w.y*s[c+1] + w.z*s[c+2] + w.w*s[c+3];
    }
    #pragma unroll
    for (int off = 8; off > 0; off >>= 1) a += __shfl_down_sync(~0u, a, off, 16);
    if (l == 0) s1[o] = fmaxf(a, 0.f);
    __syncthreads();
    float b = 0.f;
    const float4* w2p = reinterpret_cast<const float4*>(w2 + t*32);
    #pragma unroll
    for (int j = 0; j < 8; j++) {
        float4 w = w2p[j];
        b += w.x*s1[j*4+0] + w.y*s1[j*4+1] + w.z*s1[j*4+2] + w.w*s1[j*4+3];
    }
    d_scale[t] = 1.f / (1.f + expf(-b));
}

// ---- scale + sigmoid + transpose (writes [c][hw] AND [hw][c]) ----
__global__ void k_trans(const float* __restrict__ x) {
    int p0 = blockIdx.x * 32;
    int c0 = blockIdx.y * 32;
    int t = threadIdx.x;
    __shared__ float V[32][33], S[32][33];
    int r = t >> 3, q = (t & 7) * 4;
    float4 xv = *reinterpret_cast<const float4*>(x + (c0 + r)*HWN + p0 + q);
    float sc = d_scale[c0 + r];
    float4 v; v.x = xv.x*sc; v.y = xv.y*sc; v.z = xv.z*sc; v.w = xv.w*sc;
    *reinterpret_cast<float4*>(d_out32 + (c0 + r)*HWN + p0 + q) = v;
    V[r][q+0] = v.x; V[r][q+1] = v.y; V[r][q+2] = v.z; V[r][q+3] = v.w;
    S[r][q+0] = sig1(v.x);
    S[r][q+1] = sig1(v.y);
    S[r][q+2] = sig1(v.z);
    S[r][q+3] = sig1(v.w);
    __syncthreads();
    int pr = t >> 3, cq = (t & 7) * 4;
    float4 ov, sv;
    ov.x = V[cq+0][pr]; ov.y = V[cq+1][pr]; ov.z = V[cq+2][pr]; ov.w = V[cq+3][pr];
    sv.x = S[cq+0][pr]; sv.y = S[cq+1][pr]; sv.z = S[cq+2][pr]; sv.w = S[cq+3][pr];
    *reinterpret_cast<float4*>(d_out32T + (p0 + pr)*512 + c0 + cq) = ov;
    *reinterpret_cast<float4*>(d_sigT   + (p0 + pr)*512 + c0 + cq) = sv;
}

// ---- PA: blocks 0..127 FULL separable gaussian (4 ch, both stages in smem);
//      blocks 128..255 CSA score ----
__global__ void __launch_bounds__(256) k_pA() {
    __shared__ float SM[12288];   // 48KB
    int t = threadIdx.x, bid = blockIdx.x;
    if (bid < 128) {
        int c0 = bid * 4;
        float* sG  = SM;            // [1024] G[i*32+x]
        float* sGT = SM + 1024;     // [1024] GT[y*32+k]
        float* sIn = SM + 2048;     // [4][1024]
        float* sTm = SM + 6144;     // [4][1024]
        #pragma unroll
        for (int j = 0; j < 4; j++) {
            int l = t + j*256;
            sG[l]  = d_G[l];
            sGT[l] = d_G[(l & 31)*32 + (l >> 5)];
        }
        #pragma unroll
        for (int j = 0; j < 4; j++) {
            int idx = t + j*256;
            reinterpret_cast<float4*>(sIn)[idx] =
                *reinterpret_cast<const float4*>(d_out32 + (size_t)c0*1024 + idx*4);
        }
        __syncthreads();
        // stage 1: sTm[ch][i*32+y] = sum_x G[i,x]*sIn[ch][x*32+y]
        int ch = t >> 6, lane64 = t & 63;
        #pragma unroll
        for (int j = 0; j < 16; j++) {
            int e = lane64 + j*64;
            int i = e >> 5, y = e & 31;
            float acc = 0.f;
            #pragma unroll
            for (int xx = 0; xx < 32; xx++)
                acc += sG[i*32 + xx] * sIn[ch*1024 + xx*32 + y];
            sTm[ch*1024 + e] = acc;
        }
        __syncthreads();
        // stage 2: cat[p*512 + c0..c0+3] = sum_y G[k,y]*sTm[ch][i*32+y], bf16 split
        #pragma unroll
        for (int j = 0; j < 4; j++) {
            int p = t + j*256;
            int i = p >> 5, k = p & 31;
            float4 o = make_float4(0.f, 0.f, 0.f, 0.f);
            #pragma unroll
            for (int y = 0; y < 32; y++) {
                float g = sGT[y*32 + k];
                o.x += g * sTm[0*1024 + i*32 + y];
                o.y += g * sTm[1*1024 + i*32 + y];
                o.z += g * sTm[2*1024 + i*32 + y];
                o.w += g * sTm[3*1024 + i*32 + y];
            }
            uint2 hi, lo; split4(o, hi, lo);
            *reinterpret_cast<uint2*>(&d_cath[(size_t)p*512 + c0]) = hi;
            *reinterpret_cast<uint2*>(&d_catl[(size_t)p*512 + c0]) = lo;
        }
    } else {
        int b = bid - 128, h = b >> 2, ct = b & 3;
        // stage 3 rows x 32 px x 128 c of sigT (zeros for OOB rows)
        #pragma unroll
        for (int j = 0; j < 12; j++) {
            int idx = t + j*256;
            int r = idx >> 10, rem = idx & 1023;
            int w = rem >> 5, c4 = (rem & 31) * 4;
            int gh = h - 1 + r;
            float4 v = make_float4(0.f, 0.f, 0.f, 0.f);
            if (gh >= 0 && gh < 32)
                v = *reinterpret_cast<const float4*>(d_sigT + (size_t)(gh*32 + w)*512 + ct*128 + c4);
            *reinterpret_cast<float4*>(&SM[idx*4]) = v;   // r*4096 + w*128 + c4
        }
        __syncthreads();
        int warp = t >> 5, lane = t & 31, c4 = lane*4;
        #pragma unroll
        for (int wp = 0; wp < 4; wp++) {
            int w = wp*8 + warp;
            float4 cen = *reinterpret_cast<const float4*>(&SM[4096 + w*128 + c4]);
            float part[9];
            #pragma unroll
            for (int di = 0; di < 3; di++) {
                #pragma unroll
                for (int dj = 0; dj < 3; dj++) {
                    int d = di*3 + dj;
                    int gw = w + dj - 1;
                    int gwc = min(max(gw, 0), 31);
                    float s = (gw == gwc) ? 1.f : 0.f;
                    const float4 nb = *reinterpret_cast<const float4*>(&SM[di*4096 + gwc*128 + c4]);
                    part[d] = s * (cen.x*nb.x + cen.y*nb.y + cen.z*nb.z + cen.w*nb.w);
                }
            }
            #pragma unroll
            for (int d = 0; d < 9; d++) {
                float v = part[d];
                #pragma unroll
                for (int o = 16; o > 0; o >>= 1) v += __shfl_xor_sync(~0u, v, o);
                if (lane == 0) d_ps[ct*9216 + h*288 + w*9 + d] = v;
            }
        }
    }
}

// ---- PB: 128 blocks, CSA apply (softmax + weighted patch sum, bf16 out) ----
__global__ void __launch_bounds__(256) k_pB() {
    __shared__ float SM[12288];
    int t = threadIdx.x, bid = blockIdx.x;
    int h = bid >> 2, ct = bid & 3;
    int warp = t >> 5, lane = t & 31, c4 = lane*4;
    #pragma unroll
    for (int j = 0; j < 12; j++) {
        int idx = t + j*256;
        int r = idx >> 10, rem = idx & 1023;
        int w = rem >> 5, cq = (rem & 31) * 4;
        int gh = h - 1 + r;
        float4 v = make_float4(0.f, 0.f, 0.f, 0.f);
        if (gh >= 0 && gh < 32)
            v = *reinterpret_cast<const float4*>(d_out32T + (size_t)(gh*32 + w)*512 + ct*128 + cq);
        *reinterpret_cast<float4*>(&SM[idx*4]) = v;
    }
    float a[9];
    #pragma unroll
    for (int d = 0; d < 9; d++) a[d] = 0.f;
    if (lane < 4) {
        int w = lane*8 + warp;
        float s[9];
        #pragma unroll
        for (int d = 0; d < 9; d++)
            s[d] = (d_ps[0*9216 + h*288 + w*9 + d] + d_ps[1*9216 + h*288 + w*9 + d]
                  + d_ps[2*9216 + h*288 + w*9 + d] + d_ps[3*9216 + h*288 + w*9 + d])
                  * (1.f/512.f);
        float m = s[0];
        #pragma unroll
        for (int d = 1; d < 9; d++) m = fmaxf(m, s[d]);
        float ss = 0.f;
        #pragma unroll
        for (int d = 0; d < 9; d++) { a[d] = expf(s[d] - m); ss += a[d]; }
        float inv = 1.f / ss;
        #pragma unroll
        for (int d = 0; d < 9; d++) a[d] *= inv;
    }
    __syncthreads();
    #pragma unroll
    for (int wp = 0; wp < 4; wp++) {
        int w = wp*8 + warp;
        float at[9];
        #pragma unroll
        for (int d = 0; d < 9; d++) at[d] = __shfl_sync(~0u, a[d], wp);
        float4 acc = make_float4(0.f, 0.f, 0.f, 0.f);
        #pragma unroll
        for (int di = 0; di < 3; di++) {
            #pragma unroll
            for (int dj = 0; dj < 3; dj++) {
                int gw = w + dj - 1;
                int gwc = min(max(gw, 0), 31);
                float s = (gw == gwc) ? 1.f : 0.f;
                const float4 nb = *reinterpret_cast<const float4*>(&SM[di*4096 + gwc*128 + c4]);
                float av = at[di*3 + dj] * s;
                acc.x += av*nb.x; acc.y += av*nb.y; acc.z += av*nb.z; acc.w += av*nb.w;
            }
        }
        size_t f = (size_t)CHW + (size_t)(h*32 + w)*512 + ct*128 + c4;
        uint2 hi, lo; split4(acc, hi, lo);
        *reinterpret_cast<uint2*>(&d_cath[f]) = hi;
        *reinterpret_cast<uint2*>(&d_catl[f]) = lo;
    }
}

// ==================== mma.sync bf16 GEMM with preconverted operands ====
#define SMA_PITCH 80
#define SMB_PITCH 272
#define OFF_AL 10240
#define OFF_BH 20480
#define OFF_BL 29184

#define LDM_X4(r0,r1,r2,r3,addr) \
  asm volatile("ldmatrix.sync.aligned.m8n8.x4.shared.b16 {%0,%1,%2,%3},[%4];" \
    : "=r"(r0),"=r"(r1),"=r"(r2),"=r"(r3) : "r"(addr))
#define LDM_X4T(r0,r1,r2,r3,addr) \
  asm volatile("ldmatrix.sync.aligned.m8n8.x4.trans.shared.b16 {%0,%1,%2,%3},[%4];" \
    : "=r"(r0),"=r"(r1),"=r"(r2),"=r"(r3) : "r"(addr))
#define MMA(d,a,b0,b1) \
  asm volatile("mma.sync.aligned.m16n8k16.row.col.f32.bf16.bf16.f32 " \
    "{%0,%1,%2,%3},{%4,%5,%6,%7},{%8,%9},{%0,%1,%2,%3};" \
    : "+f"(d[0]),"+f"(d[1]),"+f"(d[2]),"+f"(d[3]) \
    : "r"(a[0]),"r"(a[1]),"r"(a[2]),"r"(a[3]),"r"(b0),"r"(b1))

__device__ __forceinline__ uint32_t smem_u32(const void* p) {
    uint32_t a;
    asm("{ .reg .u64 t; cvta.to.shared.u64 t, %1; cvt.u32.u64 %0, t; }" : "=r"(a) : "l"(p));
    return a;
}

__global__ void __launch_bounds__(256) k_gemm_mma() {
    __shared__ __align__(16) char sm[37888];
    uint32_t sb = smem_u32(sm);
    int t = threadIdx.x, wid = t >> 5, lane = t & 31;
    int n0 = blockIdx.x * 128;
    int m0 = blockIdx.y * 128;
    int kz = blockIdx.z * 256;
    int wm = (wid & 1) * 64, wn = (wid >> 1) * 32;

    float acc[4][4][4];
    #pragma unroll
    for (int a = 0; a < 4; a++)
        #pragma unroll
        for (int b = 0; b < 4; b++)
            #pragma unroll
            for (int cxx = 0; cxx < 4; cxx++) acc[a][b][cxx] = 0.f;

    int q = lane >> 3, r = lane & 7;
    uint32_t a_lm = sb + (uint32_t)(wm + r + ((q & 1) << 3)) * SMA_PITCH + ((q >> 1) << 3) * 2;
    uint32_t b_lm = sb + OFF_BH + (uint32_t)(r + ((q & 1) << 3)) * SMB_PITCH
                  + (uint32_t)(wn + ((q >> 1) << 3)) * 2;

    int am = t >> 1, half = t & 1;
    int bk = t >> 3, bq = t & 7;
    const __nv_bfloat16* agh = d_wh + (size_t)(m0 + am)*1024 + kz + half*16;
    const __nv_bfloat16* agl = d_wl + (size_t)(m0 + am)*1024 + kz + half*16;
    const __nv_bfloat16* bgh = d_cath + (size_t)(kz + bk)*1024 + n0 + bq*16;
    const __nv_bfloat16* bgl = d_catl + (size_t)(kz + bk)*1024 + n0 + bq*16;
    char* smaA = sm + am*SMA_PITCH + half*32;
    char* smbB = sm + OFF_BH + bk*SMB_PITCH + bq*32;

    for (int kc = 0; kc < 8; kc++) {
        uint4 pah0 = *reinterpret_cast<const uint4*>(agh + kc*32);
        uint4 pah1 = *reinterpret_cast<const uint4*>(agh + kc*32 + 8);
        uint4 pal0 = *reinterpret_cast<const uint4*>(agl + kc*32);
        uint4 pal1 = *reinterpret_cast<const uint4*>(agl + kc*32 + 8);
        uint4 pbh0 = *reinterpret_cast<const uint4*>(bgh + (size_t)kc*32*1024);
        uint4 pbh1 = *reinterpret_cast<const uint4*>(bgh + (size_t)kc*32*1024 + 8);
        uint4 pbl0 = *reinterpret_cast<const uint4*>(bgl + (size_t)kc*32*1024);
        uint4 pbl1 = *reinterpret_cast<const uint4*>(bgl + (size_t)kc*32*1024 + 8);
        __syncthreads();
        *reinterpret_cast<uint4*>(smaA) = pah0;
        *reinterpret_cast<uint4*>(smaA + 16) = pah1;
        *reinterpret_cast<uint4*>(smaA + OFF_AL) = pal0;
        *reinterpret_cast<uint4*>(smaA + OFF_AL + 16) = pal1;
        *reinterpret_cast<uint4*>(smbB) = pbh0;
        *reinterpret_cast<uint4*>(smbB + 16) = pbh1;
        *reinterpret_cast<uint4*>(smbB + (OFF_BL - OFF_BH)) = pbl0;
        *reinterpret_cast<uint4*>(smbB + (OFF_BL - OFF_BH) + 16) = pbl1;
        __syncthreads();
        #pragma unroll
        for (int ks = 0; ks < 2; ks++) {
            uint32_t ah[4][4], al[4][4], bh[2][4], bl[2][4];
            #pragma unroll
            for (int mi = 0; mi < 4; mi++) {
                uint32_t ad = a_lm + mi*16*SMA_PITCH + ks*32;
                LDM_X4(ah[mi][0], ah[mi][1], ah[mi][2], ah[mi][3], ad);
                LDM_X4(al[mi][0], al[mi][1], al[mi][2], al[mi][3], ad + OFF_AL);
            }
            #pragma unroll
            for (int nj = 0; nj < 2; nj++) {
                uint32_t bd = b_lm + nj*32 + ks*16*SMB_PITCH;
                LDM_X4T(bh[nj][0], bh[nj][1], bh[nj][2], bh[nj][3], bd);
                LDM_X4T(bl[nj][0], bl[nj][1], bl[nj][2], bl[nj][3], bd + (OFF_BL - OFF_BH));
            }
            #pragma unroll
            for (int mi = 0; mi < 4; mi++) {
                #pragma unroll
                for (int nj = 0; nj < 2; nj++) {
                    MMA(acc[mi][2*nj],   ah[mi], bh[nj][0], bh[nj][1]);
                    MMA(acc[mi][2*nj],   ah[mi], bl[nj][0], bl[nj][1]);
                    MMA(acc[mi][2*nj],   al[mi], bh[nj][0], bh[nj][1]);
                    MMA(acc[mi][2*nj+1], ah[mi], bh[nj][2], bh[nj][3]);
                    MMA(acc[mi][2*nj+1], ah[mi], bl[nj][2], bl[nj][3]);
                    MMA(acc[mi][2*nj+1], al[mi], bh[nj][2], bh[nj][3]);
                }
            }
        }
    }
    int g = lane >> 2, tq = lane & 3;
    float* base = d_y + (size_t)blockIdx.z * CHW;
    #pragma unroll
    for (int mi = 0; mi < 4; mi++) {
        int row = m0 + wm + mi*16 + g;
        #pragma unroll
        for (int ni = 0; ni < 4; ni++) {
            int col = n0 + wn + ni*8 + tq*2;
            *reinterpret_cast<float2*>(base + (size_t)row*1024 + col) =
                make_float2(acc[mi][ni][0], acc[mi][ni][1]);
            *reinterpret_cast<float2*>(base + (size_t)(row+8)*1024 + col) =
                make_float2(acc[mi][ni][2], acc[mi][ni][3]);
        }
    }
}

// ---- instance norm (+ k-split reduce) + leaky relu(0.2) ----
__global__ void k_inorm(float* __restrict__ out) {
    int o = blockIdx.x, t = threadIdx.x;
    __shared__ float red[8];
    __shared__ float bmu, brs;
    float4 v0 = reinterpret_cast<const float4*>(d_y + 0*CHW + o*1024)[t];
    float4 v1 = reinterpret_cast<const float4*>(d_y + 1*CHW + o*1024)[t];
    float4 v2 = reinterpret_cast<const float4*>(d_y + 2*CHW + o*1024)[t];
    float4 v3 = reinterpret_cast<const float4*>(d_y + 3*CHW + o*1024)[t];
    float4 v;
    v.x = (v0.x + v1.x) + (v2.x + v3.x);
    v.y = (v0.y + v1.y) + (v2.y + v3.y);
    v.z = (v0.z + v1.z) + (v2.z + v3.z);
    v.w = (v0.w + v1.w) + (v2.w + v3.w);
    float s = v.x + v.y + v.z + v.w;
    #pragma unroll
    for (int off = 16; off > 0; off >>= 1) s += __shfl_xor_sync(~0u, s, off);
    if ((t & 31) == 0) red[t >> 5] = s;
    __syncthreads();
    if (t == 0) {
        float tot = 0.f;
        #pragma unroll
        for (int w = 0; w < 8; w++) tot += red[w];
        bmu = tot * (1.f/1024.f);
    }
    __syncthreads();
    float mu = bmu;
    float dx = v.x - mu, dy = v.y - mu, dz = v.z - mu, dw = v.w - mu;
    float qq = dx*dx + dy*dy + dz*dz + dw*dw;
    #pragma unroll
    for (int off = 16; off > 0; off >>= 1) qq += __shfl_xor_sync(~0u, qq, off);
    if ((t & 31) == 0) red[t >> 5] = qq;
    __syncthreads();
    if (t == 0) {
        float tot = 0.f;
        #pragma unroll
        for (int w = 0; w < 8; w++) tot += red[w];
        brs = rsqrtf(tot * (1.f/1024.f) + 1e-5f);
    }
    __syncthreads();
    float rs = brs;
    float4 rr;
    rr.x = dx*rs; rr.y = dy*rs; rr.z = dz*rs; rr.w = dw*rs;
    rr.x = rr.x >= 0.f ? rr.x : 0.2f*rr.x;
    rr.y = rr.y >= 0.f ? rr.y : 0.2f*rr.y;
    rr.z = rr.z >= 0.f ? rr.z : 0.2f*rr.z;
    rr.w = rr.w >= 0.f ? rr.w : 0.2f*rr.w;
    reinterpret_cast<float4*>(out + o*1024)[t] = rr;
}

extern "C" void kernel_launch(void* const* d_in, const int* in_sizes, int n_in,
                              void* d_out, int out_size) {
    const float* x  = (const float*)d_in[0];
    const float* w1 = (const float*)d_in[1];
    const float* w2 = (const float*)d_in[2];
    const float* wd = (const float*)d_in[3];
    float* out = (float*)d_out;

    k_init<<<513, 256>>>(x, wd);
    k_se<<<1, 512>>>(w1, w2);
    k_trans<<<dim3(32, 16), 256>>>(x);
    k_pA<<<256, 256>>>();
    k_pB<<<128, 256>>>();
    k_gemm_mma<<<dim3(8, 4, 4), 256>>>();
    k_inorm<<<512, 256>>>(out);
}

// round 13
// speedup vs baseline: 1.0499x; 1.0499x over previous
#include <cuda_runtime.h>
#include <cuda_bf16.h>
#include <math.h>
#include <stdint.h>

#define C 512
#define HWN 1024
#define CHW (C*HWN)
#define NB 128u

__device__ __align__(16) float d_G[1024];        // G[i*32+x]
__device__ float d_mean[C];
__device__ __align__(16) float d_out32T[CHW];    // [hw][c]
__device__ __align__(16) float d_sigT[CHW];      // [hw][c]
__device__ __align__(16) float d_tmpT[CHW];      // [(i*32+y)][c]
__device__ __align__(16) float d_ps[4*1024*9];   // per-ctile partial scores
__device__ __align__(16) __nv_bfloat16 d_wh[CHW], d_wl[CHW];
__device__ __align__(16) __nv_bfloat16 d_cath[2*CHW], d_catl[2*CHW];
__device__ __align__(16) float d_y[4*CHW];       // 4 k-split partials
__device__ unsigned g_bar[8];                    // monotonic ticket barriers

__device__ __forceinline__ float tanhapx(float x) {
    float y; asm("tanh.approx.f32 %0, %1;" : "=f"(y) : "f"(x)); return y;
}
__device__ __forceinline__ float sig1(float v) {
    return fmaf(tanhapx(0.5f * v), 0.5f, 0.5f);
}
__device__ __forceinline__ uint32_t pack_bf2(float a, float b) {
    __nv_bfloat162 t(__float2bfloat16_rn(a), __float2bfloat16_rn(b));
    return *reinterpret_cast<uint32_t*>(&t);
}
__device__ __forceinline__ void split4(const float4& v, uint2& hi, uint2& lo) {
    float h0 = __bfloat162float(__float2bfloat16_rn(v.x));
    float h1 = __bfloat162float(__float2bfloat16_rn(v.y));
    float h2 = __bfloat162float(__float2bfloat16_rn(v.z));
    float h3 = __bfloat162float(__float2bfloat16_rn(v.w));
    hi = make_uint2(pack_bf2(h0, h1), pack_bf2(h2, h3));
    lo = make_uint2(pack_bf2(v.x - h0, v.y - h1), pack_bf2(v.z - h2, v.w - h3));
}
__device__ __forceinline__ uint32_t smem_u32(const void* p) {
    uint32_t a;
    asm("{ .reg .u64 t; cvta.to.shared.u64 t, %1; cvt.u32.u64 %0, t; }" : "=r"(a) : "l"(p));
    return a;
}

// ticket grid barrier: no reset needed across launches (128 | 2^32)
__device__ __forceinline__ void gridbar(int i) {
    __syncthreads();
    if (threadIdx.x == 0) {
        unsigned old, cur;
        unsigned* p = &g_bar[i];
        asm volatile("atom.release.gpu.global.add.u32 %0, [%1], %2;"
                     : "=r"(old) : "l"(p), "r"(1u) : "memory");
        unsigned target = (old / NB + 1u) * NB;
        do {
            asm volatile("ld.acquire.gpu.global.u32 %0, [%1];"
                         : "=r"(cur) : "l"(p) : "memory");
        } while (cur < target);
    }
    __syncthreads();
}

#define LDM_X4(r0,r1,r2,r3,addr) \
  asm volatile("ldmatrix.sync.aligned.m8n8.x4.shared.b16 {%0,%1,%2,%3},[%4];" \
    : "=r"(r0),"=r"(r1),"=r"(r2),"=r"(r3) : "r"(addr))
#define LDM_X4T(r0,r1,r2,r3,addr) \
  asm volatile("ldmatrix.sync.aligned.m8n8.x4.trans.shared.b16 {%0,%1,%2,%3},[%4];" \
    : "=r"(r0),"=r"(r1),"=r"(r2),"=r"(r3) : "r"(addr))
#define MMA(d,a,b0,b1) \
  asm volatile("mma.sync.aligned.m16n8k16.row.col.f32.bf16.bf16.f32 " \
    "{%0,%1,%2,%3},{%4,%5,%6,%7},{%8,%9},{%0,%1,%2,%3};" \
    : "+f"(d[0]),"+f"(d[1]),"+f"(d[2]),"+f"(d[3]) \
    : "r"(a[0]),"r"(a[1]),"r"(a[2]),"r"(a[3]),"r"(b0),"r"(b1))

#define SMA_PITCH 80
#define SMB_PITCH 272
#define OFF_AL 10240
#define OFF_BH 20480
#define OFF_BL 29184

__global__ void __launch_bounds__(256) k_fused(
    const float* __restrict__ x, const float* __restrict__ w1,
    const float* __restrict__ w2, const float* __restrict__ wd,
    float* __restrict__ out)
{
    __shared__ __align__(16) float SM[12288];   // 48KB, reused per phase
    int t = threadIdx.x, bid = blockIdx.x;

    // ================= P0: channel means + W bf16 split (512 items) + G =====
    #pragma unroll
    for (int j = 0; j < 4; j++) {
        int c = bid + j*128;
        float4 wv = *reinterpret_cast<const float4*>(wd + (size_t)c*1024 + t*4);
        uint2 hi, lo; split4(wv, hi, lo);
        *reinterpret_cast<uint2*>(&d_wh[(size_t)c*1024 + t*4]) = hi;
        *reinterpret_cast<uint2*>(&d_wl[(size_t)c*1024 + t*4]) = lo;
        float4 v = reinterpret_cast<const float4*>(x + c*HWN)[t];
        float s = v.x + v.y + v.z + v.w;
        #pragma unroll
        for (int o = 16; o > 0; o >>= 1) s += __shfl_xor_sync(~0u, s, o);
        if ((t & 31) == 0) SM[t >> 5] = s;
        __syncthreads();
        if (t == 0) {
            float tot = 0.f;
            #pragma unroll
            for (int w = 0; w < 8; w++) tot += SM[w];
            d_mean[c] = tot * (1.f/1024.f);
        }
        __syncthreads();
    }
    if (bid == 0 && t < 32) {
        int i = t;
        float ev[32]; float s = 0.f;
        #pragma unroll
        for (int xx = 0; xx < 32; xx++) {
            float dd = (float)(xx - i);
            float e = expf(-dd * dd * (1.0f/4.5f));
            ev[xx] = e; s += e;
        }
        float inv = 1.f / s;
        #pragma unroll
        for (int xx = 0; xx < 32; xx++) d_G[i*32 + xx] = ev[xx] * inv;
    }
    gridbar(0);

    // ================= SE (redundant per block, into smem) ==================
    {
        float* sMean = SM;            // [512]
        float* s1    = SM + 512;      // [32]
        float* sScale= SM + 11776;    // [512]
        sMean[t] = d_mean[t]; sMean[t + 256] = d_mean[t + 256];
        __syncthreads();
        int o = t >> 3, l = t & 7;
        float a = 0.f;
        #pragma unroll
        for (int j = 0; j < 16; j++) {
            int c = (l + j*8) * 4;
            float4 w = *reinterpret_cast<const float4*>(w1 + o*512 + c);
            a += w.x*sMean[c] + w.y*sMean[c+1] + w.z*sMean[c+2] + w.w*sMean[c+3];
        }
        #pragma unroll
        for (int off = 4; off > 0; off >>= 1) a += __shfl_down_sync(~0u, a, off, 8);
        if (l == 0) s1[o] = fmaxf(a, 0.f);
        __syncthreads();
        #pragma unroll
        for (int k = 0; k < 2; k++) {
            int oo = t + k*256;
            float b = 0.f;
            const float4* w2p = reinterpret_cast<const float4*>(w2 + oo*32);
            #pragma unroll
            for (int j = 0; j < 8; j++) {
                float4 w = w2p[j];
                b += w.x*s1[j*4+0] + w.y*s1[j*4+1] + w.z*s1[j*4+2] + w.w*s1[j*4+3];
            }
            sScale[oo] = 1.f / (1.f + expf(-b));
        }
        __syncthreads();

        // ============ P1: trans (4 tiles per block) =========================
        float* V = SM + 2048;     // [32][33]
        float* S = SM + 3104;     // [32][33]
        #pragma unroll
        for (int it = 0; it < 4; it++) {
            int tile = bid + it*128;
            int p0 = (tile & 31) * 32, c0 = (tile >> 5) * 32;
            int r = t >> 3, q = (t & 7) * 4;
            float4 xv = *reinterpret_cast<const float4*>(x + (c0 + r)*HWN + p0 + q);
            float sc = sScale[c0 + r];
            float4 v; v.x = xv.x*sc; v.y = xv.y*sc; v.z = xv.z*sc; v.w = xv.w*sc;
            V[r*33+q+0] = v.x; V[r*33+q+1] = v.y; V[r*33+q+2] = v.z; V[r*33+q+3] = v.w;
            S[r*33+q+0] = sig1(v.x);
            S[r*33+q+1] = sig1(v.y);
            S[r*33+q+2] = sig1(v.z);
            S[r*33+q+3] = sig1(v.w);
            __syncthreads();
            int pr = t >> 3, cq = (t & 7) * 4;
            float4 ov, sv;
            ov.x = V[(cq+0)*33+pr]; ov.y = V[(cq+1)*33+pr]; ov.z = V[(cq+2)*33+pr]; ov.w = V[(cq+3)*33+pr];
            sv.x = S[(cq+0)*33+pr]; sv.y = S[(cq+1)*33+pr]; sv.z = S[(cq+2)*33+pr]; sv.w = S[(cq+3)*33+pr];
            *reinterpret_cast<float4*>(d_out32T + (p0 + pr)*512 + c0 + cq) = ov;
            *reinterpret_cast<float4*>(d_sigT   + (p0 + pr)*512 + c0 + cq) = sv;
            __syncthreads();
        }
    }
    gridbar(1);

    // ================= P2: gauss stage1 + CSA score =========================
    {
        // gauss stage1 (item = bid)
        float* sG = SM; float* sm = SM + 1024;
        #pragma unroll
        for (int j = 0; j < 4; j++) sG[t + j*256] = d_G[t + j*256];
        int c0 = (bid & 3) * 128;
        int rs = bid >> 2;   // y
        #pragma unroll
        for (int j = 0; j < 4; j++) {
            int idx = t + j*256;
            int rr = idx >> 5, cq = (idx & 31) * 4;
            *reinterpret_cast<float4*>(&sm[rr*128 + cq]) =
                *reinterpret_cast<const float4*>(d_out32T + (size_t)(rr*32 + rs)*512 + c0 + cq);
        }
        __syncthreads();
        int cg = t >> 5, c4 = (t & 31) * 4;
        float4 acc[4];
        #pragma unroll
        for (int u = 0; u < 4; u++) acc[u] = make_float4(0.f, 0.f, 0.f, 0.f);
        #pragma unroll
        for (int xx = 0; xx < 32; xx += 4) {
            float4 sv0 = *reinterpret_cast<const float4*>(&sm[(xx+0)*128 + c4]);
            float4 sv1 = *reinterpret_cast<const float4*>(&sm[(xx+1)*128 + c4]);
            float4 sv2 = *reinterpret_cast<const float4*>(&sm[(xx+2)*128 + c4]);
            float4 sv3 = *reinterpret_cast<const float4*>(&sm[(xx+3)*128 + c4]);
            #pragma unroll
            for (int ii = 0; ii < 4; ii++) {
                float4 g = *reinterpret_cast<const float4*>(&sG[(cg*4+ii)*32 + xx]);
                acc[ii].x += g.x*sv0.x + g.y*sv1.x + g.z*sv2.x + g.w*sv3.x;
                acc[ii].y += g.x*sv0.y + g.y*sv1.y + g.z*sv2.y + g.w*sv3.y;
                acc[ii].z += g.x*sv0.z + g.y*sv1.z + g.z*sv2.z + g.w*sv3.z;
                acc[ii].w += g.x*sv0.w + g.y*sv1.w + g.z*sv2.w + g.w*sv3.w;
            }
        }
        #pragma unroll
        for (int ii = 0; ii < 4; ii++) {
            int i = cg*4 + ii;
            *reinterpret_cast<float4*>(d_tmpT + (size_t)(i*32 + rs)*512 + c0 + c4) = acc[ii];
        }
        __syncthreads();

        // CSA score (item = bid): h = bid>>2, ct = bid&3
        int h = bid >> 2, ct = bid & 3;
        #pragma unroll
        for (int j = 0; j < 12; j++) {
            int idx = t + j*256;
            int r = idx >> 10, rem = idx & 1023;
            int w = rem >> 5, cc = (rem & 31) * 4;
            int gh = h - 1 + r;
            float4 v = make_float4(0.f, 0.f, 0.f, 0.f);
            if (gh >= 0 && gh < 32)
                v = *reinterpret_cast<const float4*>(d_sigT + (size_t)(gh*32 + w)*512 + ct*128 + cc);
            *reinterpret_cast<float4*>(&SM[idx*4]) = v;
        }
        __syncthreads();
        int warp = t >> 5, lane = t & 31, cl4 = lane*4;
        #pragma unroll
        for (int wp = 0; wp < 4; wp++) {
            int w = wp*8 + warp;
            float4 cen = *reinterpret_cast<const float4*>(&SM[4096 + w*128 + cl4]);
            float part[9];
            #pragma unroll
            for (int di = 0; di < 3; di++) {
                #pragma unroll
                for (int dj = 0; dj < 3; dj++) {
                    int d = di*3 + dj;
                    int gw = w + dj - 1;
                    int gwc = min(max(gw, 0), 31);
                    float s = (gw == gwc) ? 1.f : 0.f;
                    const float4 nb = *reinterpret_cast<const float4*>(&SM[di*4096 + gwc*128 + cl4]);
                    part[d] = s * (cen.x*nb.x + cen.y*nb.y + cen.z*nb.z + cen.w*nb.w);
                }
            }
            #pragma unroll
            for (int d = 0; d < 9; d++) {
                float v = part[d];
                #pragma unroll
                for (int o = 16; o > 0; o >>= 1) v += __shfl_xor_sync(~0u, v, o);
                if (lane == 0) d_ps[ct*9216 + h*288 + w*9 + d] = v;
            }
        }
    }
    gridbar(2);

    // ================= P3: gauss stage2 (bf16) + CSA apply ==================
    {
        float* sG = SM; float* sm = SM + 1024;
        #pragma unroll
        for (int j = 0; j < 4; j++) sG[t + j*256] = d_G[t + j*256];
        int c0 = (bid & 3) * 128;
        int rs = bid >> 2;   // i
        #pragma unroll
        for (int j = 0; j < 4; j++) {
            int idx = t + j*256;
            int rr = idx >> 5, cq = (idx & 31) * 4;
            *reinterpret_cast<float4*>(&sm[rr*128 + cq]) =
                *reinterpret_cast<const float4*>(d_tmpT + (size_t)(rs*32 + rr)*512 + c0 + cq);
        }
        __syncthreads();
        int cg = t >> 5, c4 = (t & 31) * 4;
        float4 acc[4];
        #pragma unroll
        for (int u = 0; u < 4; u++) acc[u] = make_float4(0.f, 0.f, 0.f, 0.f);
        #pragma unroll
        for (int y = 0; y < 32; y += 4) {
            float4 sv0 = *reinterpret_cast<const float4*>(&sm[(y+0)*128 + c4]);
            float4 sv1 = *reinterpret_cast<const float4*>(&sm[(y+1)*128 + c4]);
            float4 sv2 = *reinterpret_cast<const float4*>(&sm[(y+2)*128 + c4]);
            float4 sv3 = *reinterpret_cast<const float4*>(&sm[(y+3)*128 + c4]);
            #pragma unroll
            for (int ii = 0; ii < 4; ii++) {
                float4 g = *reinterpret_cast<const float4*>(&sG[(cg*4+ii)*32 + y]);
                acc[ii].x += g.x*sv0.x + g.y*sv1.x + g.z*sv2.x + g.w*sv3.x;
                acc[ii].y += g.x*sv0.y + g.y*sv1.y + g.z*sv2.y + g.w*sv3.y;
                acc[ii].z += g.x*sv0.z + g.y*sv1.z + g.z*sv2.z + g.w*sv3.z;
                acc[ii].w += g.x*sv0.w + g.y*sv1.w + g.z*sv2.w + g.w*sv3.w;
            }
        }
        #pragma unroll
        for (int ii = 0; ii < 4; ii++) {
            int k = cg*4 + ii;
            size_t f = (size_t)(rs*32 + k)*512 + c0 + c4;
            uint2 hi, lo; split4(acc[ii], hi, lo);
            *reinterpret_cast<uint2*>(&d_cath[f]) = hi;
            *reinterpret_cast<uint2*>(&d_catl[f]) = lo;
        }
        __syncthreads();

        // CSA apply (item = bid)
        int h = bid >> 2, ct = bid & 3;
        int warp = t >> 5, lane = t & 31, cl4 = lane*4;
        #pragma unroll
        for (int j = 0; j < 12; j++) {
            int idx = t + j*256;
            int r = idx >> 10, rem = idx & 1023;
            int w = rem >> 5, cq = (rem & 31) * 4;
            int gh = h - 1 + r;
            float4 v = make_float4(0.f, 0.f, 0.f, 0.f);
            if (gh >= 0 && gh < 32)
                v = *reinterpret_cast<const float4*>(d_out32T + (size_t)(gh*32 + w)*512 + ct*128 + cq);
            *reinterpret_cast<float4*>(&SM[idx*4]) = v;
        }
        float a[9];
        #pragma unroll
        for (int d = 0; d < 9; d++) a[d] = 0.f;
        if (lane < 4) {
            int w = lane*8 + warp;
            float s[9];
            #pragma unroll
            for (int d = 0; d < 9; d++)
                s[d] = (d_ps[0*9216 + h*288 + w*9 + d] + d_ps[1*9216 + h*288 + w*9 + d]
                      + d_ps[2*9216 + h*288 + w*9 + d] + d_ps[3*9216 + h*288 + w*9 + d])
                      * (1.f/512.f);
            float m = s[0];
            #pragma unroll
            for (int d = 1; d < 9; d++) m = fmaxf(m, s[d]);
            float ss = 0.f;
            #pragma unroll
            for (int d = 0; d < 9; d++) { a[d] = expf(s[d] - m); ss += a[d]; }
            float inv = 1.f / ss;
            #pragma unroll
            for (int d = 0; d < 9; d++) a[d] *= inv;
        }
        __syncthreads();
        #pragma unroll
        for (int wp = 0; wp < 4; wp++) {
            int w = wp*8 + warp;
            float at[9];
            #pragma unroll
            for (int d = 0; d < 9; d++) at[d] = __shfl_sync(~0u, a[d], wp);
            float4 acc2 = make_float4(0.f, 0.f, 0.f, 0.f);
            #pragma unroll
            for (int di = 0; di < 3; di++) {
                #pragma unroll
                for (int dj = 0; dj < 3; dj++) {
                    int gw = w + dj - 1;
                    int gwc = min(max(gw, 0), 31);
                    float s = (gw == gwc) ? 1.f : 0.f;
                    const float4 nb = *reinterpret_cast<const float4*>(&SM[di*4096 + gwc*128 + cl4]);
                    float av = at[di*3 + dj] * s;
                    acc2.x += av*nb.x; acc2.y += av*nb.y; acc2.z += av*nb.z; acc2.w += av*nb.w;
                }
            }
            size_t f = (size_t)CHW + (size_t)(h*32 + w)*512 + ct*128 + cl4;
            uint2 hi, lo; split4(acc2, hi, lo);
            *reinterpret_cast<uint2*>(&d_cath[f]) = hi;
            *reinterpret_cast<uint2*>(&d_catl[f]) = lo;
        }
    }
    gridbar(3);

    // ================= P4: GEMM (128 tiles, one per block) ==================
    {
        char* sm = (char*)SM;
        uint32_t sb = smem_u32(sm);
        int wid = t >> 5, lane = t & 31;
        int z = bid >> 5, rem = bid & 31;
        int m0 = (rem >> 3) * 128;
        int n0 = (rem & 7) * 128;
        int kz = z * 256;
        int wm = (wid & 1) * 64, wn = (wid >> 1) * 32;

        float acc[4][4][4];
        #pragma unroll
        for (int a = 0; a < 4; a++)
            #pragma unroll
            for (int b = 0; b < 4; b++)
                #pragma unroll
                for (int cxx = 0; cxx < 4; cxx++) acc[a][b][cxx] = 0.f;

        int q = lane >> 3, r = lane & 7;
        uint32_t a_lm = sb + (uint32_t)(wm + r + ((q & 1) << 3)) * SMA_PITCH + ((q >> 1) << 3) * 2;
        uint32_t b_lm = sb + OFF_BH + (uint32_t)(r + ((q & 1) << 3)) * SMB_PITCH
                      + (uint32_t)(wn + ((q >> 1) << 3)) * 2;

        int am = t >> 1, half = t & 1;
        int bk = t >> 3, bq = t & 7;
        const __nv_bfloat16* agh = d_wh + (size_t)(m0 + am)*1024 + kz + half*16;
        const __nv_bfloat16* agl = d_wl + (size_t)(m0 + am)*1024 + kz + half*16;
        const __nv_bfloat16* bgh = d_cath + (size_t)(kz + bk)*1024 + n0 + bq*16;
        const __nv_bfloat16* bgl = d_catl + (size_t)(kz + bk)*1024 + n0 + bq*16;
        char* smaA = sm + am*SMA_PITCH + half*32;
        char* smbB = sm + OFF_BH + bk*SMB_PITCH + bq*32;

        for (int kc = 0; kc < 8; kc++) {
            uint4 pah0 = *reinterpret_cast<const uint4*>(agh + kc*32);
            uint4 pah1 = *reinterpret_cast<const uint4*>(agh + kc*32 + 8);
            uint4 pal0 = *reinterpret_cast<const uint4*>(agl + kc*32);
            uint4 pal1 = *reinterpret_cast<const uint4*>(agl + kc*32 + 8);
            uint4 pbh0 = *reinterpret_cast<const uint4*>(bgh + (size_t)kc*32*1024);
            uint4 pbh1 = *reinterpret_cast<const uint4*>(bgh + (size_t)kc*32*1024 + 8);
            uint4 pbl0 = *reinterpret_cast<const uint4*>(bgl + (size_t)kc*32*1024);
            uint4 pbl1 = *reinterpret_cast<const uint4*>(bgl + (size_t)kc*32*1024 + 8);
            __syncthreads();
            *reinterpret_cast<uint4*>(smaA) = pah0;
            *reinterpret_cast<uint4*>(smaA + 16) = pah1;
            *reinterpret_cast<uint4*>(smaA + OFF_AL) = pal0;
            *reinterpret_cast<uint4*>(smaA + OFF_AL + 16) = pal1;
            *reinterpret_cast<uint4*>(smbB) = pbh0;
            *reinterpret_cast<uint4*>(smbB + 16) = pbh1;
            *reinterpret_cast<uint4*>(smbB + (OFF_BL - OFF_BH)) = pbl0;
            *reinterpret_cast<uint4*>(smbB + (OFF_BL - OFF_BH) + 16) = pbl1;
            __syncthreads();
            #pragma unroll
            for (int ks = 0; ks < 2; ks++) {
                uint32_t ah[4][4], al[4][4], bh[2][4], bl[2][4];
                #pragma unroll
                for (int mi = 0; mi < 4; mi++) {
                    uint32_t ad = a_lm + mi*16*SMA_PITCH + ks*32;
                    LDM_X4(ah[mi][0], ah[mi][1], ah[mi][2], ah[mi][3], ad);
                    LDM_X4(al[mi][0], al[mi][1], al[mi][2], al[mi][3], ad + OFF_AL);
                }
                #pragma unroll
                for (int nj = 0; nj < 2; nj++) {
                    uint32_t bd = b_lm + nj*32 + ks*16*SMB_PITCH;
                    LDM_X4T(bh[nj][0], bh[nj][1], bh[nj][2], bh[nj][3], bd);
                    LDM_X4T(bl[nj][0], bl[nj][1], bl[nj][2], bl[nj][3], bd + (OFF_BL - OFF_BH));
                }
                #pragma unroll
                for (int mi = 0; mi < 4; mi++) {
                    #pragma unroll
                    for (int nj = 0; nj < 2; nj++) {
                        MMA(acc[mi][2*nj],   ah[mi], bh[nj][0], bh[nj][1]);
                        MMA(acc[mi][2*nj],   ah[mi], bl[nj][0], bl[nj][1]);
                        MMA(acc[mi][2*nj],   al[mi], bh[nj][0], bh[nj][1]);
                        MMA(acc[mi][2*nj+1], ah[mi], bh[nj][2], bh[nj][3]);
                        MMA(acc[mi][2*nj+1], ah[mi], bl[nj][2], bl[nj][3]);
                        MMA(acc[mi][2*nj+1], al[mi], bh[nj][2], bh[nj][3]);
                    }
                }
            }
        }
        int g = lane >> 2, tq = lane & 3;
        float* base = d_y + (size_t)z * CHW;
        #pragma unroll
        for (int mi = 0; mi < 4; mi++) {
            int row = m0 + wm + mi*16 + g;
            #pragma unroll
            for (int ni = 0; ni < 4; ni++) {
                int col = n0 + wn + ni*8 + tq*2;
                *reinterpret_cast<float2*>(base + (size_t)row*1024 + col) =
                    make_float2(acc[mi][ni][0], acc[mi][ni][1]);
                *reinterpret_cast<float2*>(base + (size_t)(row+8)*1024 + col) =
                    make_float2(acc[mi][ni][2], acc[mi][ni][3]);
            }
        }
    }
    gridbar(4);

    // ================= P5: inorm (+ reduce) + leaky relu (4 items) ==========
    #pragma unroll
    for (int j = 0; j < 4; j++) {
        int o = bid + j*128;
        float4 v0 = reinterpret_cast<const float4*>(d_y + 0*CHW + o*1024)[t];
        float4 v1 = reinterpret_cast<const float4*>(d_y + 1*CHW + o*1024)[t];
        float4 v2 = reinterpret_cast<const float4*>(d_y + 2*CHW + o*1024)[t];
        float4 v3 = reinterpret_cast<const float4*>(d_y + 3*CHW + o*1024)[t];
        float4 v;
        v.x = (v0.x + v1.x) + (v2.x + v3.x);
        v.y = (v0.y + v1.y) + (v2.y + v3.y);
        v.z = (v0.z + v1.z) + (v2.z + v3.z);
        v.w = (v0.w + v1.w) + (v2.w + v3.w);
        float s = v.x + v.y + v.z + v.w;
        #pragma unroll
        for (int off = 16; off > 0; off >>= 1) s += __shfl_xor_sync(~0u, s, off);
        if ((t & 31) == 0) SM[t >> 5] = s;
        __syncthreads();
        if (t == 0) {
            float tot = 0.f;
            #pragma unroll
            for (int w = 0; w < 8; w++) tot += SM[w];
            SM[8] = tot * (1.f/1024.f);
        }
        __syncthreads();
        float mu = SM[8];
        float dx = v.x - mu, dy = v.y - mu, dz = v.z - mu, dw = v.w - mu;
        float qq = dx*dx + dy*dy + dz*dz + dw*dw;
        #pragma unroll
        for (int off = 16; off > 0; off >>= 1) qq += __shfl_xor_sync(~0u, qq, off);
        if ((t & 31) == 0) SM[t >> 5] = qq;
        __syncthreads();
        if (t == 0) {
            float tot = 0.f;
            #pragma unroll
            for (int w = 0; w < 8; w++) tot += SM[w];
            SM[9] = rsqrtf(tot * (1.f/1024.f) + 1e-5f);
        }
        __syncthreads();
        float rs = SM[9];
        float4 rr;
        rr.x = dx*rs; rr.y = dy*rs; rr.z = dz*rs; rr.w = dw*rs;
        rr.x = rr.x >= 0.f ? rr.x : 0.2f*rr.x;
        rr.y = rr.y >= 0.f ? rr.y : 0.2f*rr.y;
        rr.z = rr.z >= 0.f ? rr.z : 0.2f*rr.z;
        rr.w = rr.w >= 0.f ? rr.w : 0.2f*rr.w;
        reinterpret_cast<float4*>(out + o*1024)[t] = rr;
        __syncthreads();
    }
}

extern "C" void kernel_launch(void* const* d_in, const int* in_sizes, int n_in,
                              void* d_out, int out_size) {
    const float* x  = (const float*)d_in[0];
    const float* w1 = (const float*)d_in[1];
    const float* w2 = (const float*)d_in[2];
    const float* wd = (const float*)d_in[3];
    float* out = (float*)d_out;

    k_fused<<<128, 256>>>(x, w1, w2, wd, out);
}

// round 14
// speedup vs baseline: 1.0523x; 1.0023x over previous
#include <cuda_runtime.h>
#include <cuda_bf16.h>
#include <math.h>
#include <stdint.h>

#define C 512
#define HWN 1024
#define CHW (C*HWN)

__device__ __align__(16) float d_G[1024];        // G[i*32+x]
__device__ float d_mean[C];
__device__ float d_scale[C];
__device__ __align__(16) float d_out32T[CHW];    // [hw][c]
__device__ __align__(16) float d_sigT[CHW];      // [hw][c]
__device__ __align__(16) float d_tmpT[CHW];      // [(i*32+y)][c]
__device__ __align__(16) float d_ps[8*1024*9];   // per-64ch-tile partial scores
__device__ __align__(16) __nv_bfloat16 d_wh[CHW], d_wl[CHW];          // W split
__device__ __align__(16) __nv_bfloat16 d_cath[2*CHW], d_catl[2*CHW];  // cat split
__device__ __align__(16) float d_y[4*CHW];       // 4 k-split partials

__device__ __forceinline__ float tanhapx(float x) {
    float y; asm("tanh.approx.f32 %0, %1;" : "=f"(y) : "f"(x)); return y;
}
__device__ __forceinline__ float sig1(float v) {
    return fmaf(tanhapx(0.5f * v), 0.5f, 0.5f);
}
__device__ __forceinline__ uint32_t pack_bf2(float a, float b) {
    __nv_bfloat162 t(__float2bfloat16_rn(a), __float2bfloat16_rn(b));
    return *reinterpret_cast<uint32_t*>(&t);
}
__device__ __forceinline__ void split4(const float4& v, uint2& hi, uint2& lo) {
    float h0 = __bfloat162float(__float2bfloat16_rn(v.x));
    float h1 = __bfloat162float(__float2bfloat16_rn(v.y));
    float h2 = __bfloat162float(__float2bfloat16_rn(v.z));
    float h3 = __bfloat162float(__float2bfloat16_rn(v.w));
    hi = make_uint2(pack_bf2(h0, h1), pack_bf2(h2, h3));
    lo = make_uint2(pack_bf2(v.x - h0, v.y - h1), pack_bf2(v.z - h2, v.w - h3));
}

// ---- blocks 0..511: channel means + W bf16 split; block 512: gaussian weights ----
__global__ void k_init(const float* __restrict__ x, const float* __restrict__ wd) {
    int t = threadIdx.x;
    if (blockIdx.x == 512) {
        int i = t;
        if (i < 32) {
            float ev[32]; float s = 0.f;
            #pragma unroll
            for (int xx = 0; xx < 32; xx++) {
                float dd = (float)(xx - i);
                float e = expf(-dd * dd * (1.0f/4.5f));
                ev[xx] = e; s += e;
            }
            float inv = 1.f / s;
            #pragma unroll
            for (int xx = 0; xx < 32; xx++) d_G[i*32 + xx] = ev[xx] * inv;
        }
        return;
    }
    int c = blockIdx.x;
    float4 wv = *reinterpret_cast<const float4*>(wd + (size_t)c*1024 + t*4);
    uint2 hi, lo; split4(wv, hi, lo);
    *reinterpret_cast<uint2*>(&d_wh[(size_t)c*1024 + t*4]) = hi;
    *reinterpret_cast<uint2*>(&d_wl[(size_t)c*1024 + t*4]) = lo;
    float4 v = reinterpret_cast<const float4*>(x + c*HWN)[t];
    float s = v.x + v.y + v.z + v.w;
    #pragma unroll
    for (int o = 16; o > 0; o >>= 1) s += __shfl_xor_sync(~0u, s, o);
    __shared__ float red[8];
    if ((t & 31) == 0) red[t >> 5] = s;
    __syncthreads();
    if (t == 0) {
        float tot = 0.f;
        #pragma unroll
        for (int w = 0; w < 8; w++) tot += red[w];
        d_mean[c] = tot * (1.f/1024.f);
    }
}

// ---- SE ----
__global__ void k_se(const float* __restrict__ w1, const float* __restrict__ w2) {
    __shared__ float s[512], s1[32];
    int t = threadIdx.x;
    s[t] = d_mean[t];
    __syncthreads();
    int o = t >> 4, l = t & 15;
    float a = 0.f;
    #pragma unroll
    for (int j = 0; j < 8; j++) {
        int c = (l + j*16) * 4;
        float4 w = *reinterpret_cast<const float4*>(w1 + o*512 + c);
        a += w.x*s[c] + w.y*s[c+1] + w.z*s[c+2] + w.w*s[c+3];
    }
    #pragma unroll
    for (int off = 8; off > 0; off >>= 1) a += __shfl_down_sync(~0u, a, off, 16);
    if (l == 0) s1[o] = fmaxf(a, 0.f);
    __syncthreads();
    float b = 0.f;
    const float4* w2p = reinterpret_cast<const float4*>(w2 + t*32);
    #pragma unroll
    for (int j = 0; j < 8; j++) {
        float4 w = w2p[j];
        b += w.x*s1[j*4+0] + w.y*s1[j*4+1] + w.z*s1[j*4+2] + w.w*s1[j*4+3];
    }
    d_scale[t] = 1.f / (1.f + expf(-b));
}

// ---- scale + sigmoid + transpose ----
__global__ void k_trans(const float* __restrict__ x) {
    int p0 = blockIdx.x * 32;
    int c0 = blockIdx.y * 32;
    int t = threadIdx.x;
    __shared__ float V[32][33], S[32][33];
    int r = t >> 3, q = (t & 7) * 4;
    float4 xv = *reinterpret_cast<const float4*>(x + (c0 + r)*HWN + p0 + q);
    float sc = d_scale[c0 + r];
    float4 v; v.x = xv.x*sc; v.y = xv.y*sc; v.z = xv.z*sc; v.w = xv.w*sc;
    V[r][q+0] = v.x; V[r][q+1] = v.y; V[r][q+2] = v.z; V[r][q+3] = v.w;
    S[r][q+0] = sig1(v.x);
    S[r][q+1] = sig1(v.y);
    S[r][q+2] = sig1(v.z);
    S[r][q+3] = sig1(v.w);
    __syncthreads();
    int pr = t >> 3, cq = (t & 7) * 4;
    float4 ov, sv;
    ov.x = V[cq+0][pr]; ov.y = V[cq+1][pr]; ov.z = V[cq+2][pr]; ov.w = V[cq+3][pr];
    sv.x = S[cq+0][pr]; sv.y = S[cq+1][pr]; sv.z = S[cq+2][pr]; sv.w = S[cq+3][pr];
    *reinterpret_cast<float4*>(d_out32T + (p0 + pr)*512 + c0 + cq) = ov;
    *reinterpret_cast<float4*>(d_sigT   + (p0 + pr)*512 + c0 + cq) = sv;
}

// ---- P1 (512 blocks): 0..255 gauss stage1 (64ch); 256..511 CSA score (64ch) ----
__global__ void __launch_bounds__(256) k_p1() {
    __shared__ float SM[6144];   // 24KB
    int t = threadIdx.x, bid = blockIdx.x;
    if (bid < 256) {
        float* sG = SM; float* sm = SM + 1024;   // sm: [x 32][c 64]
        #pragma unroll
        for (int j = 0; j < 4; j++) sG[t + j*256] = d_G[t + j*256];
        int c0 = (bid & 7) * 64;
        int rs = bid >> 3;   // y
        #pragma unroll
        for (int j = 0; j < 2; j++) {
            int idx = t + j*256;           // 512 float4 slots
            int rr = idx >> 4, cq = (idx & 15) * 4;
            *reinterpret_cast<float4*>(&sm[rr*64 + cq]) =
                *reinterpret_cast<const float4*>(d_out32T + (size_t)(rr*32 + rs)*512 + c0 + cq);
        }
        __syncthreads();
        int cg = t >> 4, c4 = (t & 15) * 4;   // cg 0..15 -> 2 i rows
        float4 acc[2];
        acc[0] = make_float4(0.f, 0.f, 0.f, 0.f);
        acc[1] = make_float4(0.f, 0.f, 0.f, 0.f);
        #pragma unroll
        for (int xx = 0; xx < 32; xx += 4) {
            float4 sv0 = *reinterpret_cast<const float4*>(&sm[(xx+0)*64 + c4]);
            float4 sv1 = *reinterpret_cast<const float4*>(&sm[(xx+1)*64 + c4]);
            float4 sv2 = *reinterpret_cast<const float4*>(&sm[(xx+2)*64 + c4]);
            float4 sv3 = *reinterpret_cast<const float4*>(&sm[(xx+3)*64 + c4]);
            #pragma unroll
            for (int ii = 0; ii < 2; ii++) {
                float4 g = *reinterpret_cast<const float4*>(&sG[(cg*2+ii)*32 + xx]);
                acc[ii].x += g.x*sv0.x + g.y*sv1.x + g.z*sv2.x + g.w*sv3.x;
                acc[ii].y += g.x*sv0.y + g.y*sv1.y + g.z*sv2.y + g.w*sv3.y;
                acc[ii].z += g.x*sv0.z + g.y*sv1.z + g.z*sv2.z + g.w*sv3.z;
                acc[ii].w += g.x*sv0.w + g.y*sv1.w + g.z*sv2.w + g.w*sv3.w;
            }
        }
        #pragma unroll
        for (int ii = 0; ii < 2; ii++) {
            int i = cg*2 + ii;
            *reinterpret_cast<float4*>(d_tmpT + (size_t)(i*32 + rs)*512 + c0 + c4) = acc[ii];
        }
    } else {
        int b = bid - 256, h = b >> 3, ct = b & 7;
        // stage 3 rows x 32 px x 64 c of sigT
        #pragma unroll
        for (int j = 0; j < 6; j++) {
            int idx = t + j*256;            // 1536 float4 slots
            int r = idx >> 9, rem = idx & 511;
            int w = rem >> 4, cc = (rem & 15) * 4;
            int gh = h - 1 + r;
            float4 v = make_float4(0.f, 0.f, 0.f, 0.f);
            if (gh >= 0 && gh < 32)
                v = *reinterpret_cast<const float4*>(d_sigT + (size_t)(gh*32 + w)*512 + ct*64 + cc);
            *reinterpret_cast<float4*>(&SM[idx*4]) = v;   // r*2048 + w*64 + cc
        }
        __syncthreads();
        int warp = t >> 5, lane = t & 31;
        int sub = lane >> 4, sl = lane & 15, c4 = sl*4;
        #pragma unroll
        for (int it = 0; it < 2; it++) {
            int w = it*16 + warp*2 + sub;
            float4 cen = *reinterpret_cast<const float4*>(&SM[2048 + w*64 + c4]);
            float part[9];
            #pragma unroll
            for (int di = 0; di < 3; di++) {
                #pragma unroll
                for (int dj = 0; dj < 3; dj++) {
                    int d = di*3 + dj;
                    int gw = w + dj - 1;
                    int gwc = min(max(gw, 0), 31);
                    float s = (gw == gwc) ? 1.f : 0.f;
                    const float4 nb = *reinterpret_cast<const float4*>(&SM[di*2048 + gwc*64 + c4]);
                    part[d] = s * (cen.x*nb.x + cen.y*nb.y + cen.z*nb.z + cen.w*nb.w);
                }
            }
            #pragma unroll
            for (int d = 0; d < 9; d++) {
                float v = part[d];
                #pragma unroll
                for (int o = 8; o > 0; o >>= 1) v += __shfl_xor_sync(~0u, v, o);
                if (sl == 0) d_ps[ct*9216 + h*288 + w*9 + d] = v;
            }
        }
    }
}

// ---- P2 (512 blocks): 0..255 gauss stage2 (64ch, bf16 out); 256..511 CSA apply ----
__global__ void __launch_bounds__(256) k_p2() {
    __shared__ float SM[6144];
    int t = threadIdx.x, bid = blockIdx.x;
    if (bid < 256) {
        float* sG = SM; float* sm = SM + 1024;
        #pragma unroll
        for (int j = 0; j < 4; j++) sG[t + j*256] = d_G[t + j*256];
        int c0 = (bid & 7) * 64;
        int rs = bid >> 3;   // i
        #pragma unroll
        for (int j = 0; j < 2; j++) {
            int idx = t + j*256;
            int rr = idx >> 4, cq = (idx & 15) * 4;
            *reinterpret_cast<float4*>(&sm[rr*64 + cq]) =
                *reinterpret_cast<const float4*>(d_tmpT + (size_t)(rs*32 + rr)*512 + c0 + cq);
        }
        __syncthreads();
        int cg = t >> 4, c4 = (t & 15) * 4;
        float4 acc[2];
        acc[0] = make_float4(0.f, 0.f, 0.f, 0.f);
        acc[1] = make_float4(0.f, 0.f, 0.f, 0.f);
        #pragma unroll
        for (int y = 0; y < 32; y += 4) {
            float4 sv0 = *reinterpret_cast<const float4*>(&sm[(y+0)*64 + c4]);
            float4 sv1 = *reinterpret_cast<const float4*>(&sm[(y+1)*64 + c4]);
            float4 sv2 = *reinterpret_cast<const float4*>(&sm[(y+2)*64 + c4]);
            float4 sv3 = *reinterpret_cast<const float4*>(&sm[(y+3)*64 + c4]);
            #pragma unroll
            for (int ii = 0; ii < 2; ii++) {
                float4 g = *reinterpret_cast<const float4*>(&sG[(cg*2+ii)*32 + y]);
                acc[ii].x += g.x*sv0.x + g.y*sv1.x + g.z*sv2.x + g.w*sv3.x;
                acc[ii].y += g.x*sv0.y + g.y*sv1.y + g.z*sv2.y + g.w*sv3.y;
                acc[ii].z += g.x*sv0.z + g.y*sv1.z + g.z*sv2.z + g.w*sv3.z;
                acc[ii].w += g.x*sv0.w + g.y*sv1.w + g.z*sv2.w + g.w*sv3.w;
            }
        }
        #pragma unroll
        for (int ii = 0; ii < 2; ii++) {
            int k = cg*2 + ii;
            size_t f = (size_t)(rs*32 + k)*512 + c0 + c4;
            uint2 hi, lo; split4(acc[ii], hi, lo);
            *reinterpret_cast<uint2*>(&d_cath[f]) = hi;
            *reinterpret_cast<uint2*>(&d_catl[f]) = lo;
        }
    } else {
        int b = bid - 256, h = b >> 3, ct = b & 7;
        int warp = t >> 5, lane = t & 31;
        int sub = lane >> 4, sl = lane & 15, c4 = sl*4;
        #pragma unroll
        for (int j = 0; j < 6; j++) {
            int idx = t + j*256;
            int r = idx >> 9, rem = idx & 511;
            int w = rem >> 4, cc = (rem & 15) * 4;
            int gh = h - 1 + r;
            float4 v = make_float4(0.f, 0.f, 0.f, 0.f);
            if (gh >= 0 && gh < 32)
                v = *reinterpret_cast<const float4*>(d_out32T + (size_t)(gh*32 + w)*512 + ct*64 + cc);
            *reinterpret_cast<float4*>(&SM[idx*4]) = v;
        }
        __syncthreads();
        #pragma unroll
        for (int it = 0; it < 2; it++) {
            int w = it*16 + warp*2 + sub;
            float a[9];
            #pragma unroll
            for (int d = 0; d < 9; d++) a[d] = 0.f;
            if (sl == 0) {
                float s[9];
                #pragma unroll
                for (int d = 0; d < 9; d++) {
                    float acc = 0.f;
                    #pragma unroll
                    for (int cc = 0; cc < 8; cc++)
                        acc += d_ps[cc*9216 + h*288 + w*9 + d];
                    s[d] = acc * (1.f/512.f);
                }
                float m = s[0];
                #pragma unroll
                for (int d = 1; d < 9; d++) m = fmaxf(m, s[d]);
                float ss = 0.f;
                #pragma unroll
                for (int d = 0; d < 9; d++) { a[d] = expf(s[d] - m); ss += a[d]; }
                float inv = 1.f / ss;
                #pragma unroll
                for (int d = 0; d < 9; d++) a[d] *= inv;
            }
            float at[9];
            #pragma unroll
            for (int d = 0; d < 9; d++) at[d] = __shfl_sync(~0u, a[d], lane & 16);
            float4 acc = make_float4(0.f, 0.f, 0.f, 0.f);
            #pragma unroll
            for (int di = 0; di < 3; di++) {
                #pragma unroll
                for (int dj = 0; dj < 3; dj++) {
                    int gw = w + dj - 1;
                    int gwc = min(max(gw, 0), 31);
                    float s = (gw == gwc) ? 1.f : 0.f;
                    const float4 nb = *reinterpret_cast<const float4*>(&SM[di*2048 + gwc*64 + c4]);
                    float av = at[di*3 + dj] * s;
                    acc.x += av*nb.x; acc.y += av*nb.y; acc.z += av*nb.z; acc.w += av*nb.w;
                }
            }
            size_t f = (size_t)CHW + (size_t)(h*32 + w)*512 + ct*64 + c4;
            uint2 hi, lo; split4(acc, hi, lo);
            *reinterpret_cast<uint2*>(&d_cath[f]) = hi;
            *reinterpret_cast<uint2*>(&d_catl[f]) = lo;
        }
    }
}

// ==================== mma.sync bf16 GEMM with preconverted operands ====
#define SMA_PITCH 80
#define SMB_PITCH 272
#define OFF_AL 10240
#define OFF_BH 20480
#define OFF_BL 29184

#define LDM_X4(r0,r1,r2,r3,addr) \
  asm volatile("ldmatrix.sync.aligned.m8n8.x4.shared.b16 {%0,%1,%2,%3},[%4];" \
    : "=r"(r0),"=r"(r1),"=r"(r2),"=r"(r3) : "r"(addr))
#define LDM_X4T(r0,r1,r2,r3,addr) \
  asm volatile("ldmatrix.sync.aligned.m8n8.x4.trans.shared.b16 {%0,%1,%2,%3},[%4];" \
    : "=r"(r0),"=r"(r1),"=r"(r2),"=r"(r3) : "r"(addr))
#define MMA(d,a,b0,b1) \
  asm volatile("mma.sync.aligned.m16n8k16.row.col.f32.bf16.bf16.f32 " \
    "{%0,%1,%2,%3},{%4,%5,%6,%7},{%8,%9},{%0,%1,%2,%3};" \
    : "+f"(d[0]),"+f"(d[1]),"+f"(d[2]),"+f"(d[3]) \
    : "r"(a[0]),"r"(a[1]),"r"(a[2]),"r"(a[3]),"r"(b0),"r"(b1))

__device__ __forceinline__ uint32_t smem_u32(const void* p) {
    uint32_t a;
    asm("{ .reg .u64 t; cvta.to.shared.u64 t, %1; cvt.u32.u64 %0, t; }" : "=r"(a) : "l"(p));
    return a;
}

__global__ void __launch_bounds__(256) k_gemm_mma() {
    __shared__ __align__(16) char sm[37888];
    uint32_t sb = smem_u32(sm);
    int t = threadIdx.x, wid = t >> 5, lane = t & 31;
    int n0 = blockIdx.x * 128;
    int m0 = blockIdx.y * 128;
    int kz = blockIdx.z * 256;
    int wm = (wid & 1) * 64, wn = (wid >> 1) * 32;

    float acc[4][4][4];
    #pragma unroll
    for (int a = 0; a < 4; a++)
        #pragma unroll
        for (int b = 0; b < 4; b++)
            #pragma unroll
            for (int cxx = 0; cxx < 4; cxx++) acc[a][b][cxx] = 0.f;

    int q = lane >> 3, r = lane & 7;
    uint32_t a_lm = sb + (uint32_t)(wm + r + ((q & 1) << 3)) * SMA_PITCH + ((q >> 1) << 3) * 2;
    uint32_t b_lm = sb + OFF_BH + (uint32_t)(r + ((q & 1) << 3)) * SMB_PITCH
                  + (uint32_t)(wn + ((q >> 1) << 3)) * 2;

    int am = t >> 1, half = t & 1;
    int bk = t >> 3, bq = t & 7;
    const __nv_bfloat16* agh = d_wh + (size_t)(m0 + am)*1024 + kz + half*16;
    const __nv_bfloat16* agl = d_wl + (size_t)(m0 + am)*1024 + kz + half*16;
    const __nv_bfloat16* bgh = d_cath + (size_t)(kz + bk)*1024 + n0 + bq*16;
    const __nv_bfloat16* bgl = d_catl + (size_t)(kz + bk)*1024 + n0 + bq*16;
    char* smaA = sm + am*SMA_PITCH + half*32;
    char* smbB = sm + OFF_BH + bk*SMB_PITCH + bq*32;

    for (int kc = 0; kc < 8; kc++) {
        uint4 pah0 = *reinterpret_cast<const uint4*>(agh + kc*32);
        uint4 pah1 = *reinterpret_cast<const uint4*>(agh + kc*32 + 8);
        uint4 pal0 = *reinterpret_cast<const uint4*>(agl + kc*32);
        uint4 pal1 = *reinterpret_cast<const uint4*>(agl + kc*32 + 8);
        uint4 pbh0 = *reinterpret_cast<const uint4*>(bgh + (size_t)kc*32*1024);
        uint4 pbh1 = *reinterpret_cast<const uint4*>(bgh + (size_t)kc*32*1024 + 8);
        uint4 pbl0 = *reinterpret_cast<const uint4*>(bgl + (size_t)kc*32*1024);
        uint4 pbl1 = *reinterpret_cast<const uint4*>(bgl + (size_t)kc*32*1024 + 8);
        __syncthreads();
        *reinterpret_cast<uint4*>(smaA) = pah0;
        *reinterpret_cast<uint4*>(smaA + 16) = pah1;
        *reinterpret_cast<uint4*>(smaA + OFF_AL) = pal0;
        *reinterpret_cast<uint4*>(smaA + OFF_AL + 16) = pal1;
        *reinterpret_cast<uint4*>(smbB) = pbh0;
        *reinterpret_cast<uint4*>(smbB + 16) = pbh1;
        *reinterpret_cast<uint4*>(smbB + (OFF_BL - OFF_BH)) = pbl0;
        *reinterpret_cast<uint4*>(smbB + (OFF_BL - OFF_BH) + 16) = pbl1;
        __syncthreads();
        #pragma unroll
        for (int ks = 0; ks < 2; ks++) {
            uint32_t ah[4][4], al[4][4], bh[2][4], bl[2][4];
            #pragma unroll
            for (int mi = 0; mi < 4; mi++) {
                uint32_t ad = a_lm + mi*16*SMA_PITCH + ks*32;
                LDM_X4(ah[mi][0], ah[mi][1], ah[mi][2], ah[mi][3], ad);
                LDM_X4(al[mi][0], al[mi][1], al[mi][2], al[mi][3], ad + OFF_AL);
            }
            #pragma unroll
            for (int nj = 0; nj < 2; nj++) {
                uint32_t bd = b_lm + nj*32 + ks*16*SMB_PITCH;
                LDM_X4T(bh[nj][0], bh[nj][1], bh[nj][2], bh[nj][3], bd);
                LDM_X4T(bl[nj][0], bl[nj][1], bl[nj][2], bl[nj][3], bd + (OFF_BL - OFF_BH));
            }
            #pragma unroll
            for (int mi = 0; mi < 4; mi++) {
                #pragma unroll
                for (int nj = 0; nj < 2; nj++) {
                    MMA(acc[mi][2*nj],   ah[mi], bh[nj][0], bh[nj][1]);
                    MMA(acc[mi][2*nj],   ah[mi], bl[nj][0], bl[nj][1]);
                    MMA(acc[mi][2*nj],   al[mi], bh[nj][0], bh[nj][1]);
                    MMA(acc[mi][2*nj+1], ah[mi], bh[nj][2], bh[nj][3]);
                    MMA(acc[mi][2*nj+1], ah[mi], bl[nj][2], bl[nj][3]);
                    MMA(acc[mi][2*nj+1], al[mi], bh[nj][2], bh[nj][3]);
                }
            }
        }
    }
    int g = lane >> 2, tq = lane & 3;
    float* base = d_y + (size_t)blockIdx.z * CHW;
    #pragma unroll
    for (int mi = 0; mi < 4; mi++) {
        int row = m0 + wm + mi*16 + g;
        #pragma unroll
        for (int ni = 0; ni < 4; ni++) {
            int col = n0 + wn + ni*8 + tq*2;
            *reinterpret_cast<float2*>(base + (size_t)row*1024 + col) =
                make_float2(acc[mi][ni][0], acc[mi][ni][1]);
            *reinterpret_cast<float2*>(base + (size_t)(row+8)*1024 + col) =
                make_float2(acc[mi][ni][2], acc[mi][ni][3]);
        }
    }
}

// ---- instance norm (+ k-split reduce) + leaky relu(0.2) ----
__global__ void k_inorm(float* __restrict__ out) {
    int o = blockIdx.x, t = threadIdx.x;
    __shared__ float red[8];
    __shared__ float bmu, brs;
    float4 v0 = reinterpret_cast<const float4*>(d_y + 0*CHW + o*1024)[t];
    float4 v1 = reinterpret_cast<const float4*>(d_y + 1*CHW + o*1024)[t];
    float4 v2 = reinterpret_cast<const float4*>(d_y + 2*CHW + o*1024)[t];
    float4 v3 = reinterpret_cast<const float4*>(d_y + 3*CHW + o*1024)[t];
    float4 v;
    v.x = (v0.x + v1.x) + (v2.x + v3.x);
    v.y = (v0.y + v1.y) + (v2.y + v3.y);
    v.z = (v0.z + v1.z) + (v2.z + v3.z);
    v.w = (v0.w + v1.w) + (v2.w + v3.w);
    float s = v.x + v.y + v.z + v.w;
    #pragma unroll
    for (int off = 16; off > 0; off >>= 1) s += __shfl_xor_sync(~0u, s, off);
    if ((t & 31) == 0) red[t >> 5] = s;
    __syncthreads();
    if (t == 0) {
        float tot = 0.f;
        #pragma unroll
        for (int w = 0; w < 8; w++) tot += red[w];
        bmu = tot * (1.f/1024.f);
    }
    __syncthreads();
    float mu = bmu;
    float dx = v.x - mu, dy = v.y - mu, dz = v.z - mu, dw = v.w - mu;
    float qq = dx*dx + dy*dy + dz*dz + dw*dw;
    #pragma unroll
    for (int off = 16; off > 0; off >>= 1) qq += __shfl_xor_sync(~0u, qq, off);
    if ((t & 31) == 0) red[t >> 5] = qq;
    __syncthreads();
    if (t == 0) {
        float tot = 0.f;
        #pragma unroll
        for (int w = 0; w < 8; w++) tot += red[w];
        brs = rsqrtf(tot * (1.f/1024.f) + 1e-5f);
    }
    __syncthreads();
    float rs = brs;
    float4 rr;
    rr.x = dx*rs; rr.y = dy*rs; rr.z = dz*rs; rr.w = dw*rs;
    rr.x = rr.x >= 0.f ? rr.x : 0.2f*rr.x;
    rr.y = rr.y >= 0.f ? rr.y : 0.2f*rr.y;
    rr.z = rr.z >= 0.f ? rr.z : 0.2f*rr.z;
    rr.w = rr.w >= 0.f ? rr.w : 0.2f*rr.w;
    reinterpret_cast<float4*>(out + o*1024)[t] = rr;
}

extern "C" void kernel_launch(void* const* d_in, const int* in_sizes, int n_in,
                              void* d_out, int out_size) {
    const float* x  = (const float*)d_in[0];
    const float* w1 = (const float*)d_in[1];
    const float* w2 = (const float*)d_in[2];
    const float* wd = (const float*)d_in[3];
    float* out = (float*)d_out;

    k_init<<<513, 256>>>(x, wd);
    k_se<<<1, 512>>>(w1, w2);
    k_trans<<<dim3(32, 16), 256>>>(x);
    k_p1<<<512, 256>>>();
    k_p2<<<512, 256>>>();
    k_gemm_mma<<<dim3(8, 4, 4), 256>>>();
    k_inorm<<<512, 256>>>(out);
}

// round 15
// speedup vs baseline: 1.1086x; 1.0535x over previous
#include <cuda_runtime.h>
#include <cuda_bf16.h>
#include <math.h>
#include <stdint.h>

#define C 512
#define HWN 1024
#define CHW (C*HWN)

__device__ __align__(16) float d_G[1024];        // G[i*32+x]
__device__ float d_mean[C];
__device__ float d_scale[C];
__device__ __align__(16) float d_out32T[CHW];    // [hw][c]
__device__ __align__(16) float d_sigT[CHW];      // [hw][c]
__device__ __align__(16) float d_tmpT[CHW];      // [(i*32+y)][c]
__device__ __align__(16) float d_ps[4*1024*9];   // per-ctile partial scores
__device__ __align__(16) __nv_bfloat16 d_wh[CHW], d_wl[CHW];          // W split
__device__ __align__(16) __nv_bfloat16 d_cath[2*CHW], d_catl[2*CHW];  // cat split
__device__ __align__(16) float d_y[4*CHW];       // 4 k-split partials

__device__ __forceinline__ float tanhapx(float x) {
    float y; asm("tanh.approx.f32 %0, %1;" : "=f"(y) : "f"(x)); return y;
}
__device__ __forceinline__ float sig1(float v) {
    return fmaf(tanhapx(0.5f * v), 0.5f, 0.5f);
}
__device__ __forceinline__ uint32_t pack_bf2(float a, float b) {
    __nv_bfloat162 t(__float2bfloat16_rn(a), __float2bfloat16_rn(b));
    return *reinterpret_cast<uint32_t*>(&t);
}
__device__ __forceinline__ void split4(const float4& v, uint2& hi, uint2& lo) {
    float h0 = __bfloat162float(__float2bfloat16_rn(v.x));
    float h1 = __bfloat162float(__float2bfloat16_rn(v.y));
    float h2 = __bfloat162float(__float2bfloat16_rn(v.z));
    float h3 = __bfloat162float(__float2bfloat16_rn(v.w));
    hi = make_uint2(pack_bf2(h0, h1), pack_bf2(h2, h3));
    lo = make_uint2(pack_bf2(v.x - h0, v.y - h1), pack_bf2(v.z - h2, v.w - h3));
}

// ---- blocks 0..511: channel means + W bf16 split; block 512: gaussian weights ----
__global__ void k_init(const float* __restrict__ x, const float* __restrict__ wd) {
    int t = threadIdx.x;
    if (blockIdx.x == 512) {
        int i = t;
        if (i < 32) {
            float ev[32]; float s = 0.f;
            #pragma unroll
            for (int xx = 0; xx < 32; xx++) {
                float dd = (float)(xx - i);
                float e = expf(-dd * dd * (1.0f/4.5f));
                ev[xx] = e; s += e;
            }
            float inv = 1.f / s;
            #pragma unroll
            for (int xx = 0; xx < 32; xx++) d_G[i*32 + xx] = ev[xx] * inv;
        }
        return;
    }
    int c = blockIdx.x;
    float4 wv = *reinterpret_cast<const float4*>(wd + (size_t)c*1024 + t*4);
    uint2 hi, lo; split4(wv, hi, lo);
    *reinterpret_cast<uint2*>(&d_wh[(size_t)c*1024 + t*4]) = hi;
    *reinterpret_cast<uint2*>(&d_wl[(size_t)c*1024 + t*4]) = lo;
    float4 v = reinterpret_cast<const float4*>(x + c*HWN)[t];
    float s = v.x + v.y + v.z + v.w;
    #pragma unroll
    for (int o = 16; o > 0; o >>= 1) s += __shfl_xor_sync(~0u, s, o);
    __shared__ float red[8];
    if ((t & 31) == 0) red[t >> 5] = s;
    __syncthreads();
    if (t == 0) {
        float tot = 0.f;
        #pragma unroll
        for (int w = 0; w < 8; w++) tot += red[w];
        d_mean[c] = tot * (1.f/1024.f);
    }
}

// ---- SE ----
__global__ void k_se(const float* __restrict__ w1, const float* __restrict__ w2) {
    __shared__ float s[512], s1[32];
    int t = threadIdx.x;
    s[t] = d_mean[t];
    __syncthreads();
    int o = t >> 4, l = t & 15;
    float a = 0.f;
    #pragma unroll
    for (int j = 0; j < 8; j++) {
        int c = (l + j*16) * 4;
        float4 w = *reinterpret_cast<const float4*>(w1 + o*512 + c);
        a += w.x*s[c] + w.y*s[c+1] + w.z*s[c+2] + w.w*s[c+3];
    }
    #pragma unroll
    for (int off = 8; off > 0; off >>= 1) a += __shfl_down_sync(~0u, a, off, 16);
    if (l == 0) s1[o] = fmaxf(a, 0.f);
    __syncthreads();
    float b = 0.f;
    const float4* w2p = reinterpret_cast<const float4*>(w2 + t*32);
    #pragma unroll
    for (int j = 0; j < 8; j++) {
        float4 w = w2p[j];
        b += w.x*s1[j*4+0] + w.y*s1[j*4+1] + w.z*s1[j*4+2] + w.w*s1[j*4+3];
    }
    d_scale[t] = 1.f / (1.f + expf(-b));
}

// ---- scale + sigmoid + transpose ----
__global__ void k_trans(const float* __restrict__ x) {
    int p0 = blockIdx.x * 32;
    int c0 = blockIdx.y * 32;
    int t = threadIdx.x;
    __shared__ float V[32][33], S[32][33];
    int r = t >> 3, q = (t & 7) * 4;
    float4 xv = *reinterpret_cast<const float4*>(x + (c0 + r)*HWN + p0 + q);
    float sc = d_scale[c0 + r];
    float4 v; v.x = xv.x*sc; v.y = xv.y*sc; v.z = xv.z*sc; v.w = xv.w*sc;
    V[r][q+0] = v.x; V[r][q+1] = v.y; V[r][q+2] = v.z; V[r][q+3] = v.w;
    S[r][q+0] = sig1(v.x);
    S[r][q+1] = sig1(v.y);
    S[r][q+2] = sig1(v.z);
    S[r][q+3] = sig1(v.w);
    __syncthreads();
    int pr = t >> 3, cq = (t & 7) * 4;
    float4 ov, sv;
    ov.x = V[cq+0][pr]; ov.y = V[cq+1][pr]; ov.z = V[cq+2][pr]; ov.w = V[cq+3][pr];
    sv.x = S[cq+0][pr]; sv.y = S[cq+1][pr]; sv.z = S[cq+2][pr]; sv.w = S[cq+3][pr];
    *reinterpret_cast<float4*>(d_out32T + (p0 + pr)*512 + c0 + cq) = ov;
    *reinterpret_cast<float4*>(d_sigT   + (p0 + pr)*512 + c0 + cq) = sv;
}

// ---- P1: blocks 0..63 gauss stage1 (256ch, 8 rows/thread); 64..191 CSA score ----
__global__ void __launch_bounds__(256) k_p1() {
    __shared__ float SM[12288];   // 48KB
    int t = threadIdx.x, bid = blockIdx.x;
    if (bid < 64) {
        float* sG = SM;            // [1024]
        float* sm = SM + 1024;     // [32 x][256 c]
        #pragma unroll
        for (int j = 0; j < 4; j++) sG[t + j*256] = d_G[t + j*256];
        int c0 = (bid & 1) * 256;
        int rs = bid >> 1;   // y
        #pragma unroll
        for (int j = 0; j < 8; j++) {
            int idx = t + j*256;           // 2048 float4 slots
            int rr = idx >> 6, cq = (idx & 63) * 4;
            *reinterpret_cast<float4*>(&sm[rr*256 + cq]) =
                *reinterpret_cast<const float4*>(d_out32T + (size_t)(rr*32 + rs)*512 + c0 + cq);
        }
        __syncthreads();
        int g = t >> 6, c4 = (t & 63) * 4;   // 4 groups x 8 i-rows
        float4 acc[8];
        #pragma unroll
        for (int u = 0; u < 8; u++) acc[u] = make_float4(0.f, 0.f, 0.f, 0.f);
        #pragma unroll
        for (int xx = 0; xx < 32; xx += 4) {
            float4 sv0 = *reinterpret_cast<const float4*>(&sm[(xx+0)*256 + c4]);
            float4 sv1 = *reinterpret_cast<const float4*>(&sm[(xx+1)*256 + c4]);
            float4 sv2 = *reinterpret_cast<const float4*>(&sm[(xx+2)*256 + c4]);
            float4 sv3 = *reinterpret_cast<const float4*>(&sm[(xx+3)*256 + c4]);
            #pragma unroll
            for (int ii = 0; ii < 8; ii++) {
                float4 gg = *reinterpret_cast<const float4*>(&sG[(g*8+ii)*32 + xx]);
                acc[ii].x += gg.x*sv0.x + gg.y*sv1.x + gg.z*sv2.x + gg.w*sv3.x;
                acc[ii].y += gg.x*sv0.y + gg.y*sv1.y + gg.z*sv2.y + gg.w*sv3.y;
                acc[ii].z += gg.x*sv0.z + gg.y*sv1.z + gg.z*sv2.z + gg.w*sv3.z;
                acc[ii].w += gg.x*sv0.w + gg.y*sv1.w + gg.z*sv2.w + gg.w*sv3.w;
            }
        }
        #pragma unroll
        for (int ii = 0; ii < 8; ii++) {
            int i = g*8 + ii;
            *reinterpret_cast<float4*>(d_tmpT + (size_t)(i*32 + rs)*512 + c0 + c4) = acc[ii];
        }
    } else {
        int b = bid - 64, h = b >> 2, ct = b & 3;
        #pragma unroll
        for (int j = 0; j < 12; j++) {
            int idx = t + j*256;
            int r = idx >> 10, rem = idx & 1023;
            int w = rem >> 5, c4 = (rem & 31) * 4;
            int gh = h - 1 + r;
            float4 v = make_float4(0.f, 0.f, 0.f, 0.f);
            if (gh >= 0 && gh < 32)
                v = *reinterpret_cast<const float4*>(d_sigT + (size_t)(gh*32 + w)*512 + ct*128 + c4);
            *reinterpret_cast<float4*>(&SM[idx*4]) = v;   // r*4096 + w*128 + c4
        }
        __syncthreads();
        int warp = t >> 5, lane = t & 31, c4 = lane*4;
        #pragma unroll
        for (int wp = 0; wp < 4; wp++) {
            int w = wp*8 + warp;
            float4 cen = *reinterpret_cast<const float4*>(&SM[4096 + w*128 + c4]);
            float part[9];
            #pragma unroll
            for (int di = 0; di < 3; di++) {
                #pragma unroll
                for (int dj = 0; dj < 3; dj++) {
                    int d = di*3 + dj;
                    int gw = w + dj - 1;
                    int gwc = min(max(gw, 0), 31);
                    float s = (gw == gwc) ? 1.f : 0.f;
                    const float4 nb = *reinterpret_cast<const float4*>(&SM[di*4096 + gwc*128 + c4]);
                    part[d] = s * (cen.x*nb.x + cen.y*nb.y + cen.z*nb.z + cen.w*nb.w);
                }
            }
            #pragma unroll
            for (int d = 0; d < 9; d++) {
                float v = part[d];
                #pragma unroll
                for (int o = 16; o > 0; o >>= 1) v += __shfl_xor_sync(~0u, v, o);
                if (lane == 0) d_ps[ct*9216 + h*288 + w*9 + d] = v;
            }
        }
    }
}

// ---- P2: blocks 0..63 gauss stage2 (256ch, bf16 out); 64..191 CSA apply ----
__global__ void __launch_bounds__(256) k_p2() {
    __shared__ float SM[12288];
    int t = threadIdx.x, bid = blockIdx.x;
    if (bid < 64) {
        float* sG = SM;
        float* sm = SM + 1024;     // [32 y][256 c]
        #pragma unroll
        for (int j = 0; j < 4; j++) sG[t + j*256] = d_G[t + j*256];
        int c0 = (bid & 1) * 256;
        int rs = bid >> 1;   // i
        #pragma unroll
        for (int j = 0; j < 8; j++) {
            int idx = t + j*256;
            int rr = idx >> 6, cq = (idx & 63) * 4;
            *reinterpret_cast<float4*>(&sm[rr*256 + cq]) =
                *reinterpret_cast<const float4*>(d_tmpT + (size_t)(rs*32 + rr)*512 + c0 + cq);
        }
        __syncthreads();
        int g = t >> 6, c4 = (t & 63) * 4;
        float4 acc[8];
        #pragma unroll
        for (int u = 0; u < 8; u++) acc[u] = make_float4(0.f, 0.f, 0.f, 0.f);
        #pragma unroll
        for (int y = 0; y < 32; y += 4) {
            float4 sv0 = *reinterpret_cast<const float4*>(&sm[(y+0)*256 + c4]);
            float4 sv1 = *reinterpret_cast<const float4*>(&sm[(y+1)*256 + c4]);
            float4 sv2 = *reinterpret_cast<const float4*>(&sm[(y+2)*256 + c4]);
            float4 sv3 = *reinterpret_cast<const float4*>(&sm[(y+3)*256 + c4]);
            #pragma unroll
            for (int ii = 0; ii < 8; ii++) {
                float4 gg = *reinterpret_cast<const float4*>(&sG[(g*8+ii)*32 + y]);
                acc[ii].x += gg.x*sv0.x + gg.y*sv1.x + gg.z*sv2.x + gg.w*sv3.x;
                acc[ii].y += gg.x*sv0.y + gg.y*sv1.y + gg.z*sv2.y + gg.w*sv3.y;
                acc[ii].z += gg.x*sv0.z + gg.y*sv1.z + gg.z*sv2.z + gg.w*sv3.z;
                acc[ii].w += gg.x*sv0.w + gg.y*sv1.w + gg.z*sv2.w + gg.w*sv3.w;
            }
        }
        #pragma unroll
        for (int ii = 0; ii < 8; ii++) {
            int k = g*8 + ii;
            size_t f = (size_t)(rs*32 + k)*512 + c0 + c4;
            uint2 hi, lo; split4(acc[ii], hi, lo);
            *reinterpret_cast<uint2*>(&d_cath[f]) = hi;
            *reinterpret_cast<uint2*>(&d_catl[f]) = lo;
        }
    } else {
        int b = bid - 64, h = b >> 2, ct = b & 3;
        int warp = t >> 5, lane = t & 31, c4 = lane*4;
        #pragma unroll
        for (int j = 0; j < 12; j++) {
            int idx = t + j*256;
            int r = idx >> 10, rem = idx & 1023;
            int w = rem >> 5, cq = (rem & 31) * 4;
            int gh = h - 1 + r;
            float4 v = make_float4(0.f, 0.f, 0.f, 0.f);
            if (gh >= 0 && gh < 32)
                v = *reinterpret_cast<const float4*>(d_out32T + (size_t)(gh*32 + w)*512 + ct*128 + cq);
            *reinterpret_cast<float4*>(&SM[idx*4]) = v;
        }
        float a[9];
        #pragma unroll
        for (int d = 0; d < 9; d++) a[d] = 0.f;
        if (lane < 4) {
            int w = lane*8 + warp;
            float s[9];
            #pragma unroll
            for (int d = 0; d < 9; d++)
                s[d] = (d_ps[0*9216 + h*288 + w*9 + d] + d_ps[1*9216 + h*288 + w*9 + d]
                      + d_ps[2*9216 + h*288 + w*9 + d] + d_ps[3*9216 + h*288 + w*9 + d])
                      * (1.f/512.f);
            float m = s[0];
            #pragma unroll
            for (int d = 1; d < 9; d++) m = fmaxf(m, s[d]);
            float ss = 0.f;
            #pragma unroll
            for (int d = 0; d < 9; d++) { a[d] = expf(s[d] - m); ss += a[d]; }
            float inv = 1.f / ss;
            #pragma unroll
            for (int d = 0; d < 9; d++) a[d] *= inv;
        }
        __syncthreads();
        #pragma unroll
        for (int wp = 0; wp < 4; wp++) {
            int w = wp*8 + warp;
            float at[9];
            #pragma unroll
            for (int d = 0; d < 9; d++) at[d] = __shfl_sync(~0u, a[d], wp);
            float4 acc = make_float4(0.f, 0.f, 0.f, 0.f);
            #pragma unroll
            for (int di = 0; di < 3; di++) {
                #pragma unroll
                for (int dj = 0; dj < 3; dj++) {
                    int gw = w + dj - 1;
                    int gwc = min(max(gw, 0), 31);
                    float s = (gw == gwc) ? 1.f : 0.f;
                    const float4 nb = *reinterpret_cast<const float4*>(&SM[di*4096 + gwc*128 + c4]);
                    float av = at[di*3 + dj] * s;
                    acc.x += av*nb.x; acc.y += av*nb.y; acc.z += av*nb.z; acc.w += av*nb.w;
                }
            }
            size_t f = (size_t)CHW + (size_t)(h*32 + w)*512 + ct*128 + c4;
            uint2 hi, lo; split4(acc, hi, lo);
            *reinterpret_cast<uint2*>(&d_cath[f]) = hi;
            *reinterpret_cast<uint2*>(&d_catl[f]) = lo;
        }
    }
}

// ==================== mma.sync bf16 GEMM with preconverted operands ====
#define SMA_PITCH 80
#define SMB_PITCH 272
#define OFF_AL 10240
#define OFF_BH 20480
#define OFF_BL 29184

#define LDM_X4(r0,r1,r2,r3,addr) \
  asm volatile("ldmatrix.sync.aligned.m8n8.x4.shared.b16 {%0,%1,%2,%3},[%4];" \
    : "=r"(r0),"=r"(r1),"=r"(r2),"=r"(r3) : "r"(addr))
#define LDM_X4T(r0,r1,r2,r3,addr) \
  asm volatile("ldmatrix.sync.aligned.m8n8.x4.trans.shared.b16 {%0,%1,%2,%3},[%4];" \
    : "=r"(r0),"=r"(r1),"=r"(r2),"=r"(r3) : "r"(addr))
#define MMA(d,a,b0,b1) \
  asm volatile("mma.sync.aligned.m16n8k16.row.col.f32.bf16.bf16.f32 " \
    "{%0,%1,%2,%3},{%4,%5,%6,%7},{%8,%9},{%0,%1,%2,%3};" \
    : "+f"(d[0]),"+f"(d[1]),"+f"(d[2]),"+f"(d[3]) \
    : "r"(a[0]),"r"(a[1]),"r"(a[2]),"r"(a[3]),"r"(b0),"r"(b1))

__device__ __forceinline__ uint32_t smem_u32(const void* p) {
    uint32_t a;
    asm("{ .reg .u64 t; cvta.to.shared.u64 t, %1; cvt.u32.u64 %0, t; }" : "=r"(a) : "l"(p));
    return a;
}

__global__ void __launch_bounds__(256) k_gemm_mma() {
    __shared__ __align__(16) char sm[37888];
    uint32_t sb = smem_u32(sm);
    int t = threadIdx.x, wid = t >> 5, lane = t & 31;
    int n0 = blockIdx.x * 128;
    int m0 = blockIdx.y * 128;
    int kz = blockIdx.z * 256;
    int wm = (wid & 1) * 64, wn = (wid >> 1) * 32;

    float acc[4][4][4];
    #pragma unroll
    for (int a = 0; a < 4; a++)
        #pragma unroll
        for (int b = 0; b < 4; b++)
            #pragma unroll
            for (int cxx = 0; cxx < 4; cxx++) acc[a][b][cxx] = 0.f;

    int q = lane >> 3, r = lane & 7;
    uint32_t a_lm = sb + (uint32_t)(wm + r + ((q & 1) << 3)) * SMA_PITCH + ((q >> 1) << 3) * 2;
    uint32_t b_lm = sb + OFF_BH + (uint32_t)(r + ((q & 1) << 3)) * SMB_PITCH
                  + (uint32_t)(wn + ((q >> 1) << 3)) * 2;

    int am = t >> 1, half = t & 1;
    int bk = t >> 3, bq = t & 7;
    const __nv_bfloat16* agh = d_wh + (size_t)(m0 + am)*1024 + kz + half*16;
    const __nv_bfloat16* agl = d_wl + (size_t)(m0 + am)*1024 + kz + half*16;
    const __nv_bfloat16* bgh = d_cath + (size_t)(kz + bk)*1024 + n0 + bq*16;
    const __nv_bfloat16* bgl = d_catl + (size_t)(kz + bk)*1024 + n0 + bq*16;
    char* smaA = sm + am*SMA_PITCH + half*32;
    char* smbB = sm + OFF_BH + bk*SMB_PITCH + bq*32;

    for (int kc = 0; kc < 8; kc++) {
        uint4 pah0 = *reinterpret_cast<const uint4*>(agh + kc*32);
        uint4 pah1 = *reinterpret_cast<const uint4*>(agh + kc*32 + 8);
        uint4 pal0 = *reinterpret_cast<const uint4*>(agl + kc*32);
        uint4 pal1 = *reinterpret_cast<const uint4*>(agl + kc*32 + 8);
        uint4 pbh0 = *reinterpret_cast<const uint4*>(bgh + (size_t)kc*32*1024);
        uint4 pbh1 = *reinterpret_cast<const uint4*>(bgh + (size_t)kc*32*1024 + 8);
        uint4 pbl0 = *reinterpret_cast<const uint4*>(bgl + (size_t)kc*32*1024);
        uint4 pbl1 = *reinterpret_cast<const uint4*>(bgl + (size_t)kc*32*1024 + 8);
        __syncthreads();
        *reinterpret_cast<uint4*>(smaA) = pah0;
        *reinterpret_cast<uint4*>(smaA + 16) = pah1;
        *reinterpret_cast<uint4*>(smaA + OFF_AL) = pal0;
        *reinterpret_cast<uint4*>(smaA + OFF_AL + 16) = pal1;
        *reinterpret_cast<uint4*>(smbB) = pbh0;
        *reinterpret_cast<uint4*>(smbB + 16) = pbh1;
        *reinterpret_cast<uint4*>(smbB + (OFF_BL - OFF_BH)) = pbl0;
        *reinterpret_cast<uint4*>(smbB + (OFF_BL - OFF_BH) + 16) = pbl1;
        __syncthreads();
        #pragma unroll
        for (int ks = 0; ks < 2; ks++) {
            uint32_t ah[4][4], al[4][4], bh[2][4], bl[2][4];
            #pragma unroll
            for (int mi = 0; mi < 4; mi++) {
                uint32_t ad = a_lm + mi*16*SMA_PITCH + ks*32;
                LDM_X4(ah[mi][0], ah[mi][1], ah[mi][2], ah[mi][3], ad);
                LDM_X4(al[mi][0], al[mi][1], al[mi][2], al[mi][3], ad + OFF_AL);
            }
            #pragma unroll
            for (int nj = 0; nj < 2; nj++) {
                uint32_t bd = b_lm + nj*32 + ks*16*SMB_PITCH;
                LDM_X4T(bh[nj][0], bh[nj][1], bh[nj][2], bh[nj][3], bd);
                LDM_X4T(bl[nj][0], bl[nj][1], bl[nj][2], bl[nj][3], bd + (OFF_BL - OFF_BH));
            }
            #pragma unroll
            for (int mi = 0; mi < 4; mi++) {
                #pragma unroll
                for (int nj = 0; nj < 2; nj++) {
                    MMA(acc[mi][2*nj],   ah[mi], bh[nj][0], bh[nj][1]);
                    MMA(acc[mi][2*nj],   ah[mi], bl[nj][0], bl[nj][1]);
                    MMA(acc[mi][2*nj],   al[mi], bh[nj][0], bh[nj][1]);
                    MMA(acc[mi][2*nj+1], ah[mi], bh[nj][2], bh[nj][3]);
                    MMA(acc[mi][2*nj+1], ah[mi], bl[nj][2], bl[nj][3]);
                    MMA(acc[mi][2*nj+1], al[mi], bh[nj][2], bh[nj][3]);
                }
            }
        }
    }
    int g = lane >> 2, tq = lane & 3;
    float* base = d_y + (size_t)blockIdx.z * CHW;
    #pragma unroll
    for (int mi = 0; mi < 4; mi++) {
        int row = m0 + wm + mi*16 + g;
        #pragma unroll
        for (int ni = 0; ni < 4; ni++) {
            int col = n0 + wn + ni*8 + tq*2;
            *reinterpret_cast<float2*>(base + (size_t)row*1024 + col) =
                make_float2(acc[mi][ni][0], acc[mi][ni][1]);
            *reinterpret_cast<float2*>(base + (size_t)(row+8)*1024 + col) =
                make_float2(acc[mi][ni][2], acc[mi][ni][3]);
        }
    }
}

// ---- instance norm (+ k-split reduce) + leaky relu(0.2) ----
__global__ void k_inorm(float* __restrict__ out) {
    int o = blockIdx.x, t = threadIdx.x;
    __shared__ float red[8];
    __shared__ float bmu, brs;
    float4 v0 = reinterpret_cast<const float4*>(d_y + 0*CHW + o*1024)[t];
    float4 v1 = reinterpret_cast<const float4*>(d_y + 1*CHW + o*1024)[t];
    float4 v2 = reinterpret_cast<const float4*>(d_y + 2*CHW + o*1024)[t];
    float4 v3 = reinterpret_cast<const float4*>(d_y + 3*CHW + o*1024)[t];
    float4 v;
    v.x = (v0.x + v1.x) + (v2.x + v3.x);
    v.y = (v0.y + v1.y) + (v2.y + v3.y);
    v.z = (v0.z + v1.z) + (v2.z + v3.z);
    v.w = (v0.w + v1.w) + (v2.w + v3.w);
    float s = v.x + v.y + v.z + v.w;
    #pragma unroll
    for (int off = 16; off > 0; off >>= 1) s += __shfl_xor_sync(~0u, s, off);
    if ((t & 31) == 0) red[t >> 5] = s;
    __syncthreads();
    if (t == 0) {
        float tot = 0.f;
        #pragma unroll
        for (int w = 0; w < 8; w++) tot += red[w];
        bmu = tot * (1.f/1024.f);
    }
    __syncthreads();
    float mu = bmu;
    float dx = v.x - mu, dy = v.y - mu, dz = v.z - mu, dw = v.w - mu;
    float qq = dx*dx + dy*dy + dz*dz + dw*dw;
    #pragma unroll
    for (int off = 16; off > 0; off >>= 1) qq += __shfl_xor_sync(~0u, qq, off);
    if ((t & 31) == 0) red[t >> 5] = qq;
    __syncthreads();
    if (t == 0) {
        float tot = 0.f;
        #pragma unroll
        for (int w = 0; w < 8; w++) tot += red[w];
        brs = rsqrtf(tot * (1.f/1024.f) + 1e-5f);
    }
    __syncthreads();
    float rs = brs;
    float4 rr;
    rr.x = dx*rs; rr.y = dy*rs; rr.z = dz*rs; rr.w = dw*rs;
    rr.x = rr.x >= 0.f ? rr.x : 0.2f*rr.x;
    rr.y = rr.y >= 0.f ? rr.y : 0.2f*rr.y;
    rr.z = rr.z >= 0.f ? rr.z : 0.2f*rr.z;
    rr.w = rr.w >= 0.f ? rr.w : 0.2f*rr.w;
    reinterpret_cast<float4*>(out + o*1024)[t] = rr;
}

extern "C" void kernel_launch(void* const* d_in, const int* in_sizes, int n_in,
                              void* d_out, int out_size) {
    const float* x  = (const float*)d_in[0];
    const float* w1 = (const float*)d_in[1];
    const float* w2 = (const float*)d_in[2];
    const float* wd = (const float*)d_in[3];
    float* out = (float*)d_out;

    k_init<<<513, 256>>>(x, wd);
    k_se<<<1, 512>>>(w1, w2);
    k_trans<<<dim3(32, 16), 256>>>(x);
    k_p1<<<192, 256>>>();
    k_p2<<<192, 256>>>();
    k_gemm_mma<<<dim3(8, 4, 4), 256>>>();
    k_inorm<<<512, 256>>>(out);
}